// round 1
// baseline (speedup 1.0000x reference)
#include <cuda_runtime.h>
#include <cuda_bf16.h>
#include <math.h>

#define N_NODES 20000
#define N_EDGES 200000
#define CH 64
#define HC 256
#define NHEAD 4

// ---------------- scratch (static device globals; no runtime alloc) ----------------
__device__ float    g_h[N_NODES * CH];
__device__ float    g_f[N_EDGES * CH];
__device__ float    g_hni[N_NODES * HC];
__device__ float    g_hnj[N_NODES * HC];
__device__ float    g_hproj[N_NODES * HC];
__device__ float    g_fproj[N_EDGES * HC];
__device__ float    g_score[N_EDGES * NHEAD];
__device__ float    g_denom[N_NODES * NHEAD];
__device__ unsigned g_smax[N_NODES * NHEAD];
__device__ float    g_hacc[N_NODES * CH];

// ---------------- helpers ----------------
__device__ __forceinline__ unsigned fenc(float f) {
    unsigned u = __float_as_uint(f);
    return (u & 0x80000000u) ? ~u : (u | 0x80000000u);
}
__device__ __forceinline__ float fdec(unsigned u) {
    return (u & 0x80000000u) ? __uint_as_float(u ^ 0x80000000u)
                             : __uint_as_float(~u);
}
__device__ __forceinline__ float eluf(float x) { return x > 0.f ? x : expm1f(x); }
__device__ __forceinline__ float warp_sum(float v) {
#pragma unroll
    for (int o = 16; o; o >>= 1) v += __shfl_xor_sync(0xffffffffu, v, o);
    return v;
}

// ---------------- SGEMM: C[M,Nt] = A[M,K] @ B[K,Nt] (+bias) ----------------
// block computes a 64x64 tile; 256 threads, each a 4x4 register tile.
__global__ void gemm64(const float* __restrict__ A, const float* __restrict__ B,
                       const float* __restrict__ bias, float* __restrict__ Cout,
                       int M, int K, int Nt) {
    __shared__ __align__(16) float sAt[65][68];  // [k][row]
    __shared__ __align__(16) float sB[65][68];   // [k][col]
    const int row0 = blockIdx.x * 64;
    const int col0 = blockIdx.y * 64;
    const int tid = threadIdx.x;

    for (int idx = tid; idx < 64 * K; idx += 256) {
        int r = idx / K, k = idx - r * K;
        float av = (row0 + r < M) ? A[(size_t)(row0 + r) * K + k] : 0.f;
        sAt[k][r] = av;
    }
    for (int idx = tid; idx < K * 64; idx += 256) {
        int k = idx >> 6, c = idx & 63;
        sB[k][c] = B[(size_t)k * Nt + col0 + c];
    }
    __syncthreads();

    const int tx = tid & 15, ty = tid >> 4;
    float acc[4][4];
#pragma unroll
    for (int i = 0; i < 4; i++)
#pragma unroll
        for (int j = 0; j < 4; j++) acc[i][j] = 0.f;

#pragma unroll 4
    for (int k = 0; k < K; k++) {
        float4 a4 = *(const float4*)&sAt[k][ty * 4];
        float4 b4 = *(const float4*)&sB[k][tx * 4];
        float aa[4] = {a4.x, a4.y, a4.z, a4.w};
        float bb[4] = {b4.x, b4.y, b4.z, b4.w};
#pragma unroll
        for (int i = 0; i < 4; i++)
#pragma unroll
            for (int j = 0; j < 4; j++) acc[i][j] += aa[i] * bb[j];
    }

    float bv[4];
#pragma unroll
    for (int j = 0; j < 4; j++) bv[j] = bias ? bias[col0 + tx * 4 + j] : 0.f;

#pragma unroll
    for (int i = 0; i < 4; i++) {
        int r = row0 + ty * 4 + i;
        if (r < M) {
            size_t base = (size_t)r * Nt + col0 + tx * 4;
#pragma unroll
            for (int j = 0; j < 4; j++) Cout[base + j] = acc[i][j] + bv[j];
        }
    }
}

// ---------------- per-layer init ----------------
__global__ void init_layer() {
    int idx = blockIdx.x * blockDim.x + threadIdx.x;
    if (idx < N_NODES * CH) g_hacc[idx] = 0.f;
    if (idx < N_NODES * NHEAD) {
        g_denom[idx] = 0.f;
        g_smax[idx] = 0x007fffffu;  // encoded -inf
    }
}

// ---------------- edge pass 1: f_out, scores, segment-max, next-layer f ----------------
// one warp per edge; f_out = hni[src] + hnj[dst] + fproj[e]  (bias_e folded into fproj)
__global__ void edge_pass1(const int* __restrict__ src, const int* __restrict__ dst,
                           const float* __restrict__ attn_l) {
    int e = (blockIdx.x * blockDim.x + threadIdx.x) >> 5;
    if (e >= N_EDGES) return;
    int lane = threadIdx.x & 31;
    int s = src[e], d = dst[e];
    const float* pni = g_hni + (size_t)s * HC;
    const float* pnj = g_hnj + (size_t)d * HC;
    const float* pfp = g_fproj + (size_t)e * HC;

    float v[8];
#pragma unroll
    for (int j = 0; j < 8; j++) {
        int idx = lane + 32 * j;
        v[j] = pni[idx] + pnj[idx] + pfp[idx];
    }

    // per-head attention scores: sum_c leaky_relu(v) * attn[h][c]
    float p[NHEAD];
#pragma unroll
    for (int h = 0; h < NHEAD; h++) {
        float a0 = attn_l[h * 64 + lane];
        float a1 = attn_l[h * 64 + lane + 32];
        float x0 = v[2 * h], x1 = v[2 * h + 1];
        float l0 = x0 > 0.f ? x0 : 0.01f * x0;
        float l1 = x1 > 0.f ? x1 : 0.01f * x1;
        p[h] = l0 * a0 + l1 * a1;
    }
#pragma unroll
    for (int o = 16; o; o >>= 1) {
#pragma unroll
        for (int h = 0; h < NHEAD; h++)
            p[h] += __shfl_xor_sync(0xffffffffu, p[h], o);
    }
    if (lane < NHEAD) {
        g_score[e * NHEAD + lane] = p[lane];
        atomicMax(&g_smax[(size_t)d * NHEAD + lane], fenc(p[lane]));
    }

    // next-layer f: elu(instnorm(mean over heads of f_out))
    float m0 = 0.25f * (v[0] + v[2] + v[4] + v[6]);  // channel = lane
    float m1 = 0.25f * (v[1] + v[3] + v[5] + v[7]);  // channel = lane+32
    float sum = warp_sum(m0 + m1);
    float sq = warp_sum(m0 * m0 + m1 * m1);
    float mean = sum * (1.f / 64.f);
    float var = sq * (1.f / 64.f) - mean * mean;
    float rs = rsqrtf(var + 1e-5f);
    g_f[(size_t)e * CH + lane] = eluf((m0 - mean) * rs);
    g_f[(size_t)e * CH + lane + 32] = eluf((m1 - mean) * rs);
}

// ---------------- edge pass 2: w = exp(score - smax[dst]); denom += w ----------------
__global__ void edge_pass2(const int* __restrict__ dst) {
    int idx = blockIdx.x * blockDim.x + threadIdx.x;
    if (idx >= N_EDGES * NHEAD) return;
    int e = idx >> 2, h = idx & 3;
    int d = dst[e];
    float mx = fdec(g_smax[(size_t)d * NHEAD + h]);
    float w = __expf(g_score[idx] - mx);
    g_score[idx] = w;
    atomicAdd(&g_denom[(size_t)d * NHEAD + h], w);
}

// ---------------- edge pass 3: head-mean of a*hproj[src], scatter into hacc[dst] ----------------
__global__ void edge_pass3(const int* __restrict__ src, const int* __restrict__ dst) {
    int e = (blockIdx.x * blockDim.x + threadIdx.x) >> 5;
    if (e >= N_EDGES) return;
    int lane = threadIdx.x & 31;
    int s = src[e], d = dst[e];
    float a0 = g_score[e * NHEAD + 0] / g_denom[(size_t)d * NHEAD + 0];
    float a1 = g_score[e * NHEAD + 1] / g_denom[(size_t)d * NHEAD + 1];
    float a2 = g_score[e * NHEAD + 2] / g_denom[(size_t)d * NHEAD + 2];
    float a3 = g_score[e * NHEAD + 3] / g_denom[(size_t)d * NHEAD + 3];
    const float* hp = g_hproj + (size_t)s * HC;
    float acc0 = 0.25f * (hp[lane] * a0 + hp[64 + lane] * a1 +
                          hp[128 + lane] * a2 + hp[192 + lane] * a3);
    float acc1 = 0.25f * (hp[32 + lane] * a0 + hp[96 + lane] * a1 +
                          hp[160 + lane] * a2 + hp[224 + lane] * a3);
    atomicAdd(&g_hacc[(size_t)d * CH + lane], acc0);
    atomicAdd(&g_hacc[(size_t)d * CH + lane + 32], acc1);
}

// ---------------- node norm: h = elu(instnorm(hacc)) ----------------
__global__ void node_norm() {
    int n = (blockIdx.x * blockDim.x + threadIdx.x) >> 5;
    if (n >= N_NODES) return;
    int lane = threadIdx.x & 31;
    float m0 = g_hacc[(size_t)n * CH + lane];
    float m1 = g_hacc[(size_t)n * CH + lane + 32];
    float sum = warp_sum(m0 + m1);
    float sq = warp_sum(m0 * m0 + m1 * m1);
    float mean = sum * (1.f / 64.f);
    float var = sq * (1.f / 64.f) - mean * mean;
    float rs = rsqrtf(var + 1e-5f);
    g_h[(size_t)n * CH + lane] = eluf((m0 - mean) * rs);
    g_h[(size_t)n * CH + lane + 32] = eluf((m1 - mean) * rs);
}

// ---------------- launcher ----------------
extern "C" void kernel_launch(void* const* d_in, const int* in_sizes, int n_in,
                              void* d_out, int out_size) {
    const float* x = (const float*)d_in[0];
    const float* efeat = (const float*)d_in[1];
    const int* src = (const int*)d_in[2];
    const int* dst = (const int*)d_in[3];
    const float* Wn0 = (const float*)d_in[4];
    const float* bn0 = (const float*)d_in[5];
    const float* We0 = (const float*)d_in[6];
    const float* be0 = (const float*)d_in[7];
    const float* Wnode = (const float*)d_in[8];
    const float* bnode = (const float*)d_in[9];
    const float* Wni = (const float*)d_in[10];
    const float* Wnj = (const float*)d_in[11];
    const float* Wfij = (const float*)d_in[12];
    const float* attn = (const float*)d_in[13];
    const float* bias_e = (const float*)d_in[14];
    const float* Wf = (const float*)d_in[15];
    const float* bf = (const float*)d_in[16];

    float *ph, *pf, *phni, *phnj, *phproj, *pfproj;
    cudaGetSymbolAddress((void**)&ph, g_h);
    cudaGetSymbolAddress((void**)&pf, g_f);
    cudaGetSymbolAddress((void**)&phni, g_hni);
    cudaGetSymbolAddress((void**)&phnj, g_hnj);
    cudaGetSymbolAddress((void**)&phproj, g_hproj);
    cudaGetSymbolAddress((void**)&pfproj, g_fproj);

    const dim3 blk(256);
    const int NB_N = (N_NODES + 63) / 64;   // 313
    const int NB_E = (N_EDGES + 63) / 64;   // 3125

    // input projections
    gemm64<<<dim3(NB_N, 1), blk>>>(x, Wn0, bn0, ph, N_NODES, 65, 64);
    gemm64<<<dim3(NB_E, 1), blk>>>(efeat, We0, be0, pf, N_EDGES, 15, 64);

    for (int l = 0; l < 2; l++) {
        const float* Wni_l = Wni + (size_t)l * 64 * 256;
        const float* Wnj_l = Wnj + (size_t)l * 64 * 256;
        const float* Wnode_l = Wnode + (size_t)l * 64 * 256;
        const float* Wfij_l = Wfij + (size_t)l * 64 * 256;
        const float* bnode_l = bnode + (size_t)l * 256;
        const float* bias_e_l = bias_e + (size_t)l * 256;
        const float* attn_l = attn + (size_t)l * 256;

        init_layer<<<(N_NODES * CH + 255) / 256, blk>>>();
        gemm64<<<dim3(NB_N, 4), blk>>>(ph, Wni_l, nullptr, phni, N_NODES, 64, 256);
        gemm64<<<dim3(NB_N, 4), blk>>>(ph, Wnj_l, nullptr, phnj, N_NODES, 64, 256);
        gemm64<<<dim3(NB_N, 4), blk>>>(ph, Wnode_l, bnode_l, phproj, N_NODES, 64, 256);
        gemm64<<<dim3(NB_E, 4), blk>>>(pf, Wfij_l, bias_e_l, pfproj, N_EDGES, 64, 256);

        edge_pass1<<<(N_EDGES * 32 + 255) / 256, blk>>>(src, dst, attn_l);
        edge_pass2<<<(N_EDGES * NHEAD + 255) / 256, blk>>>(dst);
        edge_pass3<<<(N_EDGES * 32 + 255) / 256, blk>>>(src, dst);
        node_norm<<<(N_NODES * 32 + 255) / 256, blk>>>();
    }

    gemm64<<<dim3(NB_N, 1), blk>>>(ph, Wf, bf, (float*)d_out, N_NODES, 64, 64);
}

// round 3
// speedup vs baseline: 1.1433x; 1.1433x over previous
#include <cuda_runtime.h>
#include <cuda_bf16.h>
#include <math.h>
#include <stdint.h>

#define N_NODES 20000
#define N_EDGES 200000
#define CH 64
#define HC 256
#define NHEAD 4

// ---------------- scratch (static device globals; no runtime alloc) ----------------
__device__ __align__(256) float    g_h[N_NODES * CH];
__device__ __align__(256) float    g_f[N_EDGES * CH];
__device__ __align__(256) __nv_bfloat16 g_hs[N_NODES * 128];    // split bf16 (hi|lo)
__device__ __align__(256) __nv_bfloat16 g_fs[N_EDGES * 128];    // split bf16 (hi|lo)
__device__ __align__(256) __nv_bfloat16 g_wprep[8 * 256 * 192]; // prepped weights [n][k']
__device__ __align__(256) float    g_hni[N_NODES * HC];
__device__ __align__(256) float    g_hnj[N_NODES * HC];
__device__ __align__(256) float    g_hproj[N_NODES * HC];
__device__ __align__(256) float    g_fproj[N_EDGES * HC];
__device__ __align__(256) float    g_score[N_EDGES * NHEAD];
__device__ __align__(256) float    g_denom[N_NODES * NHEAD];
__device__ __align__(256) unsigned g_smax[N_NODES * NHEAD];
__device__ __align__(256) float    g_hacc[N_NODES * CH];

// ---------------- helpers ----------------
__device__ __forceinline__ uint32_t smem_u32(const void* p) {
    uint32_t a;
    asm("{ .reg .u64 t; cvta.to.shared.u64 t, %1; cvt.u32.u64 %0, t; }" : "=r"(a) : "l"(p));
    return a;
}
__device__ __forceinline__ unsigned fenc(float f) {
    unsigned u = __float_as_uint(f);
    return (u & 0x80000000u) ? ~u : (u | 0x80000000u);
}
__device__ __forceinline__ float fdec(unsigned u) {
    return (u & 0x80000000u) ? __uint_as_float(u ^ 0x80000000u) : __uint_as_float(~u);
}
__device__ __forceinline__ float eluf(float x) { return x > 0.f ? x : expm1f(x); }
__device__ __forceinline__ float warp_sum(float v) {
#pragma unroll
    for (int o = 16; o; o >>= 1) v += __shfl_xor_sync(0xffffffffu, v, o);
    return v;
}
__device__ __forceinline__ void ldm_x4(uint32_t* r, uint32_t addr) {
    asm volatile("ldmatrix.sync.aligned.m8n8.x4.shared.b16 {%0,%1,%2,%3}, [%4];"
                 : "=r"(r[0]), "=r"(r[1]), "=r"(r[2]), "=r"(r[3]) : "r"(addr));
}
__device__ __forceinline__ void mma_bf16(float* d, const uint32_t* a, const uint32_t* b) {
    asm volatile("mma.sync.aligned.m16n8k16.row.col.f32.bf16.bf16.f32 "
                 "{%0,%1,%2,%3}, {%4,%5,%6,%7}, {%8,%9}, {%0,%1,%2,%3};"
                 : "+f"(d[0]), "+f"(d[1]), "+f"(d[2]), "+f"(d[3])
                 : "r"(a[0]), "r"(a[1]), "r"(a[2]), "r"(a[3]), "r"(b[0]), "r"(b[1]));
}

// ============ mma.sync GEMM: C[M,256] = A[M,64] @ W[64,256] (+bias), 3xBF16 split ============
// A: split pairs [M,128] (hi|lo). Wp: prepped [256,192] (K-concat hi;lo;hi per N-row).
// smem A' [128][200] k-cols (hi|hi|lo), smem B [256][200].
#define MM_SMEM 153600
#define SMB_OFF 51200
__global__ void __launch_bounds__(512, 1)
gemm_mma(const __nv_bfloat16* __restrict__ A, const __nv_bfloat16* __restrict__ Wp,
         const float* __restrict__ bias, float* __restrict__ C, int M) {
    extern __shared__ __align__(1024) char smem[];
    __nv_bfloat16* smA = (__nv_bfloat16*)smem;
    __nv_bfloat16* smB = (__nv_bfloat16*)(smem + SMB_OFF);
    const int tid = threadIdx.x;
    const int w = tid >> 5, lane = tid & 31;
    const int row0 = blockIdx.x * 128;

    // fill A': 128 rows x 192 cols ([hi | hi | lo] in k'), pad stride 200
    for (int u = tid; u < 3072; u += 512) {
        int m = u / 24, k0 = (u - m * 24) * 8;
        int sc = (k0 & 63) + (k0 >= 128 ? 64 : 0);
        uint4 v = make_uint4(0, 0, 0, 0);
        if (row0 + m < M) v = *(const uint4*)(A + (size_t)(row0 + m) * 128 + sc);
        *(uint4*)(smA + m * 200 + k0) = v;
    }
    // fill B: [n=256][k'=192], pad stride 200
    for (int u = tid; u < 6144; u += 512) {
        int n = u / 24, k0 = (u - n * 24) * 8;
        *(uint4*)(smB + n * 200 + k0) = *(const uint4*)(Wp + (size_t)n * 192 + k0);
    }
    __syncthreads();

    const int mw = (w >> 3) * 64;   // warp row base (0/64)
    const int nw = (w & 7) * 32;    // warp col base
    const int g = lane >> 3, r = lane & 7;

    float acc[4][4][4];
#pragma unroll
    for (int i = 0; i < 4; i++)
#pragma unroll
        for (int j = 0; j < 4; j++)
#pragma unroll
            for (int q = 0; q < 4; q++) acc[i][j][q] = 0.f;

    // ldmatrix lane addresses (bytes). A x4 tiles: [m0-7,k0-7][m8-15,k0-7][m0-7,k8-15][m8-15,k8-15]
    uint32_t aAddr = smem_u32(smA) + ((mw + (g & 1) * 8 + r) * 200 + (g >> 1) * 8) * 2;
    // B x4 tiles: [n0-7,k0-7][n0-7,k8-15][n8-15,k0-7][n8-15,k8-15]
    uint32_t bAddr = smem_u32(smB) + ((nw + (g >> 1) * 8 + r) * 200 + (g & 1) * 8) * 2;

    for (int ks = 0; ks < 12; ks++) {
        uint32_t af[4][4], bf[2][4];
#pragma unroll
        for (int i = 0; i < 4; i++) ldm_x4(af[i], aAddr + i * 6400);   // 16 rows * 400B
#pragma unroll
        for (int p = 0; p < 2; p++) ldm_x4(bf[p], bAddr + p * 6400);
#pragma unroll
        for (int i = 0; i < 4; i++)
#pragma unroll
            for (int j = 0; j < 4; j++)
                mma_bf16(acc[i][j], af[i], &bf[j >> 1][(j & 1) * 2]);
        aAddr += 32;  // 16 bf16 in k
        bAddr += 32;
    }

    // epilogue: stage through smem for coalesced output
    __syncthreads();
    float* stage = (float*)smem;  // [128][260]
#pragma unroll
    for (int i = 0; i < 4; i++)
#pragma unroll
        for (int j = 0; j < 4; j++) {
            int m = mw + i * 16 + (lane >> 2);
            int n = nw + j * 8 + (lane & 3) * 2;
            stage[m * 260 + n] = acc[i][j][0];
            stage[m * 260 + n + 1] = acc[i][j][1];
            stage[(m + 8) * 260 + n] = acc[i][j][2];
            stage[(m + 8) * 260 + n + 1] = acc[i][j][3];
        }
    __syncthreads();
    int rows = min(128, M - row0);
    for (int u = tid; u < rows * 64; u += 512) {
        int m2 = u >> 6, c4 = (u & 63) * 4;
        float4 v = *(float4*)(stage + m2 * 260 + c4);
        if (bias) {
            float4 bb = *(const float4*)(bias + c4);
            v.x += bb.x; v.y += bb.y; v.z += bb.z; v.w += bb.w;
        }
        *(float4*)(C + (size_t)(row0 + m2) * 256 + c4) = v;
    }
}

// ---------------- fp32 SGEMM (small input/output projections) ----------------
__global__ void gemm64(const float* __restrict__ A, const float* __restrict__ B,
                       const float* __restrict__ bias, float* __restrict__ Cout,
                       int M, int K, int Nt) {
    __shared__ __align__(16) float sAt[65][68];
    __shared__ __align__(16) float sB[65][68];
    const int row0 = blockIdx.x * 64;
    const int col0 = blockIdx.y * 64;
    const int tid = threadIdx.x;

    for (int idx = tid; idx < 64 * K; idx += 256) {
        int r = idx / K, k = idx - r * K;
        sAt[k][r] = (row0 + r < M) ? A[(size_t)(row0 + r) * K + k] : 0.f;
    }
    for (int idx = tid; idx < K * 64; idx += 256) {
        int k = idx >> 6, c = idx & 63;
        sB[k][c] = B[(size_t)k * Nt + col0 + c];
    }
    __syncthreads();

    const int tx = tid & 15, ty = tid >> 4;
    float acc[4][4];
#pragma unroll
    for (int i = 0; i < 4; i++)
#pragma unroll
        for (int j = 0; j < 4; j++) acc[i][j] = 0.f;

#pragma unroll 4
    for (int k = 0; k < K; k++) {
        float4 a4 = *(const float4*)&sAt[k][ty * 4];
        float4 b4 = *(const float4*)&sB[k][tx * 4];
        float aa[4] = {a4.x, a4.y, a4.z, a4.w};
        float bb[4] = {b4.x, b4.y, b4.z, b4.w};
#pragma unroll
        for (int i = 0; i < 4; i++)
#pragma unroll
            for (int j = 0; j < 4; j++) acc[i][j] += aa[i] * bb[j];
    }
    float bv[4];
#pragma unroll
    for (int j = 0; j < 4; j++) bv[j] = bias ? bias[col0 + tx * 4 + j] : 0.f;
#pragma unroll
    for (int i = 0; i < 4; i++) {
        int r = row0 + ty * 4 + i;
        if (r < M) {
            size_t base = (size_t)r * Nt + col0 + tx * 4;
#pragma unroll
            for (int j = 0; j < 4; j++) Cout[base + j] = acc[i][j] + bv[j];
        }
    }
}

// ---------------- split / weight-prep ----------------
__global__ void split_pair(const float* __restrict__ src, __nv_bfloat16* __restrict__ dst, int M) {
    int idx = blockIdx.x * blockDim.x + threadIdx.x;
    if (idx >= M * 64) return;
    int m = idx >> 6, c = idx & 63;
    float v = src[idx];
    __nv_bfloat16 hi = __float2bfloat16(v);
    dst[(size_t)m * 128 + c] = hi;
    dst[(size_t)m * 128 + 64 + c] = __float2bfloat16(v - __bfloat162float(hi));
}
// W [64,256] fp32 -> Wp [256,192] bf16, rows are N, K-concat (hi ; lo ; hi)
__global__ void prep_weight(const float* __restrict__ W, __nv_bfloat16* __restrict__ Wp) {
    int idx = blockIdx.x * blockDim.x + threadIdx.x;
    if (idx >= 256 * 192) return;
    int n = idx / 192, kk = idx - n * 192;
    int k = kk & 63;
    float v = W[(size_t)k * 256 + n];
    __nv_bfloat16 hi = __float2bfloat16(v);
    __nv_bfloat16 out = hi;
    if (kk >= 64 && kk < 128) out = __float2bfloat16(v - __bfloat162float(hi));
    Wp[idx] = out;
}

// ---------------- per-layer init ----------------
__global__ void init_layer() {
    int idx = blockIdx.x * blockDim.x + threadIdx.x;
    if (idx < N_NODES * CH) g_hacc[idx] = 0.f;
    if (idx < N_NODES * NHEAD) {
        g_denom[idx] = 0.f;
        g_smax[idx] = 0x007fffffu;
    }
}

// ---------------- edge pass 1 ----------------
__global__ void edge_pass1(const int* __restrict__ src, const int* __restrict__ dst,
                           const float* __restrict__ attn_l) {
    int e = (blockIdx.x * blockDim.x + threadIdx.x) >> 5;
    if (e >= N_EDGES) return;
    int lane = threadIdx.x & 31;
    int s = src[e], d = dst[e];
    const float* pni = g_hni + (size_t)s * HC;
    const float* pnj = g_hnj + (size_t)d * HC;
    const float* pfp = g_fproj + (size_t)e * HC;

    float v[8];
#pragma unroll
    for (int j = 0; j < 8; j++) {
        int idx = lane + 32 * j;
        v[j] = pni[idx] + pnj[idx] + pfp[idx];
    }
    float p[NHEAD];
#pragma unroll
    for (int h = 0; h < NHEAD; h++) {
        float a0 = attn_l[h * 64 + lane];
        float a1 = attn_l[h * 64 + lane + 32];
        float x0 = v[2 * h], x1 = v[2 * h + 1];
        float l0 = x0 > 0.f ? x0 : 0.01f * x0;
        float l1 = x1 > 0.f ? x1 : 0.01f * x1;
        p[h] = l0 * a0 + l1 * a1;
    }
#pragma unroll
    for (int o = 16; o; o >>= 1) {
#pragma unroll
        for (int h = 0; h < NHEAD; h++)
            p[h] += __shfl_xor_sync(0xffffffffu, p[h], o);
    }
    if (lane < NHEAD) {
        g_score[e * NHEAD + lane] = p[lane];
        atomicMax(&g_smax[(size_t)d * NHEAD + lane], fenc(p[lane]));
    }
    // next-layer f (split bf16, elu(instnorm(head-mean)))
    float m0 = 0.25f * (v[0] + v[2] + v[4] + v[6]);
    float m1 = 0.25f * (v[1] + v[3] + v[5] + v[7]);
    float sum = warp_sum(m0 + m1);
    float sq = warp_sum(m0 * m0 + m1 * m1);
    float mean = sum * (1.f / 64.f);
    float var = sq * (1.f / 64.f) - mean * mean;
    float rs = rsqrtf(var + 1e-5f);
    float f0 = eluf((m0 - mean) * rs);
    float f1 = eluf((m1 - mean) * rs);
    __nv_bfloat16 h0 = __float2bfloat16(f0);
    __nv_bfloat16 h1 = __float2bfloat16(f1);
    size_t b = (size_t)e * 128;
    g_fs[b + lane] = h0;
    g_fs[b + lane + 32] = h1;
    g_fs[b + 64 + lane] = __float2bfloat16(f0 - __bfloat162float(h0));
    g_fs[b + 96 + lane] = __float2bfloat16(f1 - __bfloat162float(h1));
}

// ---------------- edge pass 2 ----------------
__global__ void edge_pass2(const int* __restrict__ dst) {
    int idx = blockIdx.x * blockDim.x + threadIdx.x;
    if (idx >= N_EDGES * NHEAD) return;
    int e = idx >> 2, h = idx & 3;
    int d = dst[e];
    float mx = fdec(g_smax[(size_t)d * NHEAD + h]);
    float w = __expf(g_score[idx] - mx);
    g_score[idx] = w;
    atomicAdd(&g_denom[(size_t)d * NHEAD + h], w);
}

// ---------------- edge pass 3 ----------------
__global__ void edge_pass3(const int* __restrict__ src, const int* __restrict__ dst) {
    int e = (blockIdx.x * blockDim.x + threadIdx.x) >> 5;
    if (e >= N_EDGES) return;
    int lane = threadIdx.x & 31;
    int s = src[e], d = dst[e];
    float a0 = g_score[e * NHEAD + 0] / g_denom[(size_t)d * NHEAD + 0];
    float a1 = g_score[e * NHEAD + 1] / g_denom[(size_t)d * NHEAD + 1];
    float a2 = g_score[e * NHEAD + 2] / g_denom[(size_t)d * NHEAD + 2];
    float a3 = g_score[e * NHEAD + 3] / g_denom[(size_t)d * NHEAD + 3];
    const float* hp = g_hproj + (size_t)s * HC;
    float acc0 = 0.25f * (hp[lane] * a0 + hp[64 + lane] * a1 +
                          hp[128 + lane] * a2 + hp[192 + lane] * a3);
    float acc1 = 0.25f * (hp[32 + lane] * a0 + hp[96 + lane] * a1 +
                          hp[160 + lane] * a2 + hp[224 + lane] * a3);
    atomicAdd(&g_hacc[(size_t)d * CH + lane], acc0);
    atomicAdd(&g_hacc[(size_t)d * CH + lane + 32], acc1);
}

// ---------------- node norm ----------------
__global__ void node_norm() {
    int n = (blockIdx.x * blockDim.x + threadIdx.x) >> 5;
    if (n >= N_NODES) return;
    int lane = threadIdx.x & 31;
    float m0 = g_hacc[(size_t)n * CH + lane];
    float m1 = g_hacc[(size_t)n * CH + lane + 32];
    float sum = warp_sum(m0 + m1);
    float sq = warp_sum(m0 * m0 + m1 * m1);
    float mean = sum * (1.f / 64.f);
    float var = sq * (1.f / 64.f) - mean * mean;
    float rs = rsqrtf(var + 1e-5f);
    float h0 = eluf((m0 - mean) * rs);
    float h1 = eluf((m1 - mean) * rs);
    g_h[(size_t)n * CH + lane] = h0;
    g_h[(size_t)n * CH + lane + 32] = h1;
    __nv_bfloat16 b0 = __float2bfloat16(h0);
    __nv_bfloat16 b1 = __float2bfloat16(h1);
    size_t b = (size_t)n * 128;
    g_hs[b + lane] = b0;
    g_hs[b + lane + 32] = b1;
    g_hs[b + 64 + lane] = __float2bfloat16(h0 - __bfloat162float(b0));
    g_hs[b + 96 + lane] = __float2bfloat16(h1 - __bfloat162float(b1));
}

// ---------------- launcher ----------------
extern "C" void kernel_launch(void* const* d_in, const int* in_sizes, int n_in,
                              void* d_out, int out_size) {
    const float* x = (const float*)d_in[0];
    const float* efeat = (const float*)d_in[1];
    const int* src = (const int*)d_in[2];
    const int* dst = (const int*)d_in[3];
    const float* Wn0 = (const float*)d_in[4];
    const float* bn0 = (const float*)d_in[5];
    const float* We0 = (const float*)d_in[6];
    const float* be0 = (const float*)d_in[7];
    const float* Wnode = (const float*)d_in[8];
    const float* bnode = (const float*)d_in[9];
    const float* Wni = (const float*)d_in[10];
    const float* Wnj = (const float*)d_in[11];
    const float* Wfij = (const float*)d_in[12];
    const float* attn = (const float*)d_in[13];
    const float* bias_e = (const float*)d_in[14];
    const float* Wf = (const float*)d_in[15];
    const float* bf = (const float*)d_in[16];

    float *ph, *pf, *phni, *phnj, *phproj, *pfproj;
    __nv_bfloat16 *phs, *pfs, *pwp;
    cudaGetSymbolAddress((void**)&ph, g_h);
    cudaGetSymbolAddress((void**)&pf, g_f);
    cudaGetSymbolAddress((void**)&phni, g_hni);
    cudaGetSymbolAddress((void**)&phnj, g_hnj);
    cudaGetSymbolAddress((void**)&phproj, g_hproj);
    cudaGetSymbolAddress((void**)&pfproj, g_fproj);
    cudaGetSymbolAddress((void**)&phs, g_hs);
    cudaGetSymbolAddress((void**)&pfs, g_fs);
    cudaGetSymbolAddress((void**)&pwp, g_wprep);

    cudaFuncSetAttribute(gemm_mma, cudaFuncAttributeMaxDynamicSharedMemorySize, MM_SMEM);

    const dim3 blk(256);
    const int NB_N = (N_NODES + 63) / 64;
    const int NB_E = (N_EDGES + 63) / 64;
    const int TB_N = (N_NODES + 127) / 128;   // 157
    const int TB_E = (N_EDGES + 127) / 128;   // 1563
    const int WPSZ = 256 * 192;

    for (int l = 0; l < 2; l++) {
        prep_weight<<<192, blk>>>(Wni + (size_t)l * 64 * 256, pwp + (size_t)(l * 4 + 0) * WPSZ);
        prep_weight<<<192, blk>>>(Wnj + (size_t)l * 64 * 256, pwp + (size_t)(l * 4 + 1) * WPSZ);
        prep_weight<<<192, blk>>>(Wnode + (size_t)l * 64 * 256, pwp + (size_t)(l * 4 + 2) * WPSZ);
        prep_weight<<<192, blk>>>(Wfij + (size_t)l * 64 * 256, pwp + (size_t)(l * 4 + 3) * WPSZ);
    }

    gemm64<<<dim3(NB_N, 1), blk>>>(x, Wn0, bn0, ph, N_NODES, 65, 64);
    gemm64<<<dim3(NB_E, 1), blk>>>(efeat, We0, be0, pf, N_EDGES, 15, 64);
    split_pair<<<(N_NODES * 64 + 255) / 256, blk>>>(ph, phs, N_NODES);
    split_pair<<<(N_EDGES * 64 + 255) / 256, blk>>>(pf, pfs, N_EDGES);

    for (int l = 0; l < 2; l++) {
        const float* bnode_l = bnode + (size_t)l * 256;
        const float* bias_e_l = bias_e + (size_t)l * 256;
        const float* attn_l = attn + (size_t)l * 256;

        init_layer<<<(N_NODES * CH + 255) / 256, blk>>>();
        gemm_mma<<<TB_N, 512, MM_SMEM>>>(phs, pwp + (size_t)(l * 4 + 0) * WPSZ, nullptr, phni, N_NODES);
        gemm_mma<<<TB_N, 512, MM_SMEM>>>(phs, pwp + (size_t)(l * 4 + 1) * WPSZ, nullptr, phnj, N_NODES);
        gemm_mma<<<TB_N, 512, MM_SMEM>>>(phs, pwp + (size_t)(l * 4 + 2) * WPSZ, bnode_l, phproj, N_NODES);
        gemm_mma<<<TB_E, 512, MM_SMEM>>>(pfs, pwp + (size_t)(l * 4 + 3) * WPSZ, bias_e_l, pfproj, N_EDGES);

        edge_pass1<<<(N_EDGES * 32 + 255) / 256, blk>>>(src, dst, attn_l);
        edge_pass2<<<(N_EDGES * NHEAD + 255) / 256, blk>>>(dst);
        edge_pass3<<<(N_EDGES * 32 + 255) / 256, blk>>>(src, dst);
        node_norm<<<(N_NODES * 32 + 255) / 256, blk>>>();
    }

    gemm64<<<dim3(NB_N, 1), blk>>>(ph, Wf, bf, (float*)d_out, N_NODES, 64, 64);
}

// round 4
// speedup vs baseline: 1.3018x; 1.1386x over previous
#include <cuda_runtime.h>
#include <cuda_bf16.h>
#include <math.h>
#include <stdint.h>

#define N_NODES 20000
#define N_EDGES 200000
#define CH 64
#define HC 256
#define NHEAD 4

// ---------------- scratch ----------------
__device__ __align__(256) float    g_h[N_NODES * CH];
__device__ __align__(256) __nv_bfloat16 g_hs[N_NODES * 128];
__device__ __align__(256) __nv_bfloat16 g_fs[N_EDGES * 128];
__device__ __align__(256) __nv_bfloat16 g_wprep[8 * 256 * 192];
__device__ __align__(256) float    g_hni[N_NODES * HC];
__device__ __align__(256) float    g_hnj[N_NODES * HC];
__device__ __align__(256) float    g_hproj[N_NODES * HC];
__device__ __align__(256) float    g_score[N_EDGES * NHEAD];
__device__ __align__(256) float    g_denom[N_NODES * NHEAD];
__device__ __align__(256) unsigned g_smax[N_NODES * NHEAD];
__device__ __align__(256) float    g_hacc[N_NODES * CH];

// ---------------- helpers ----------------
__device__ __forceinline__ uint32_t smem_u32(const void* p) {
    uint32_t a;
    asm("{ .reg .u64 t; cvta.to.shared.u64 t, %1; cvt.u32.u64 %0, t; }" : "=r"(a) : "l"(p));
    return a;
}
__device__ __forceinline__ unsigned fenc(float f) {
    unsigned u = __float_as_uint(f);
    return (u & 0x80000000u) ? ~u : (u | 0x80000000u);
}
__device__ __forceinline__ float fdec(unsigned u) {
    return (u & 0x80000000u) ? __uint_as_float(u ^ 0x80000000u) : __uint_as_float(~u);
}
__device__ __forceinline__ float eluf(float x) { return x > 0.f ? x : expm1f(x); }
__device__ __forceinline__ float warp_sum(float v) {
#pragma unroll
    for (int o = 16; o; o >>= 1) v += __shfl_xor_sync(0xffffffffu, v, o);
    return v;
}
__device__ __forceinline__ void ldm_x4(uint32_t* r, uint32_t addr) {
    asm volatile("ldmatrix.sync.aligned.m8n8.x4.shared.b16 {%0,%1,%2,%3}, [%4];"
                 : "=r"(r[0]), "=r"(r[1]), "=r"(r[2]), "=r"(r[3]) : "r"(addr));
}
__device__ __forceinline__ void mma_bf16(float* d, const uint32_t* a, const uint32_t* b) {
    asm volatile("mma.sync.aligned.m16n8k16.row.col.f32.bf16.bf16.f32 "
                 "{%0,%1,%2,%3}, {%4,%5,%6,%7}, {%8,%9}, {%0,%1,%2,%3};"
                 : "+f"(d[0]), "+f"(d[1]), "+f"(d[2]), "+f"(d[3])
                 : "r"(a[0]), "r"(a[1]), "r"(a[2]), "r"(a[3]), "r"(b[0]), "r"(b[1]));
}

#define MM_SMEM 153600
#define SMB_OFF 51200

// ======== core mma tile: fills smem, runs 12 k-steps, stages C into smem stage ========
// stage layout: float [128][260] at smem base. Returns after final __syncthreads.
__device__ __forceinline__ void mma_tile_to_stage(
    char* smem, const __nv_bfloat16* __restrict__ A, const __nv_bfloat16* __restrict__ Wp,
    int row0, int M, int tid, int w, int lane) {
    __nv_bfloat16* smA = (__nv_bfloat16*)smem;
    __nv_bfloat16* smB = (__nv_bfloat16*)(smem + SMB_OFF);

    for (int u = tid; u < 3072; u += 512) {
        int m = u / 24, k0 = (u - m * 24) * 8;
        int sc = (k0 & 63) + (k0 >= 128 ? 64 : 0);
        uint4 v = make_uint4(0, 0, 0, 0);
        if (row0 + m < M) v = *(const uint4*)(A + (size_t)(row0 + m) * 128 + sc);
        *(uint4*)(smA + m * 200 + k0) = v;
    }
    for (int u = tid; u < 6144; u += 512) {
        int n = u / 24, k0 = (u - n * 24) * 8;
        *(uint4*)(smB + n * 200 + k0) = *(const uint4*)(Wp + (size_t)n * 192 + k0);
    }
    __syncthreads();

    const int mw = (w >> 3) * 64;
    const int nw = (w & 7) * 32;
    const int g = lane >> 3, r = lane & 7;

    float acc[4][4][4];
#pragma unroll
    for (int i = 0; i < 4; i++)
#pragma unroll
        for (int j = 0; j < 4; j++)
#pragma unroll
            for (int q = 0; q < 4; q++) acc[i][j][q] = 0.f;

    uint32_t aAddr = smem_u32(smA) + ((mw + (g & 1) * 8 + r) * 200 + (g >> 1) * 8) * 2;
    uint32_t bAddr = smem_u32(smB) + ((nw + (g >> 1) * 8 + r) * 200 + (g & 1) * 8) * 2;

    for (int ks = 0; ks < 12; ks++) {
        uint32_t af[4][4], bf[2][4];
#pragma unroll
        for (int i = 0; i < 4; i++) ldm_x4(af[i], aAddr + i * 6400);
#pragma unroll
        for (int p = 0; p < 2; p++) ldm_x4(bf[p], bAddr + p * 6400);
#pragma unroll
        for (int i = 0; i < 4; i++)
#pragma unroll
            for (int j = 0; j < 4; j++)
                mma_bf16(acc[i][j], af[i], &bf[j >> 1][(j & 1) * 2]);
        aAddr += 32;
        bAddr += 32;
    }

    __syncthreads();
    float* stage = (float*)smem;
#pragma unroll
    for (int i = 0; i < 4; i++)
#pragma unroll
        for (int j = 0; j < 4; j++) {
            int m = mw + i * 16 + (lane >> 2);
            int n = nw + j * 8 + (lane & 3) * 2;
            stage[m * 260 + n] = acc[i][j][0];
            stage[m * 260 + n + 1] = acc[i][j][1];
            stage[(m + 8) * 260 + n] = acc[i][j][2];
            stage[(m + 8) * 260 + n + 1] = acc[i][j][3];
        }
}

// ======== node GEMMs: 3 weights in one launch (y=0:ni, 1:nj, 2:node+bias) ========
__global__ void __launch_bounds__(512, 1)
gemm_node3(const __nv_bfloat16* __restrict__ A, const __nv_bfloat16* __restrict__ WpBase,
           const float* __restrict__ bnode_l,
           float* __restrict__ Cni, float* __restrict__ Cnj, float* __restrict__ Cnode) {
    extern __shared__ __align__(1024) char smem[];
    const int tid = threadIdx.x, w = tid >> 5, lane = tid & 31;
    const int row0 = blockIdx.x * 128;
    const int y = blockIdx.y;
    const __nv_bfloat16* Wp = WpBase + (size_t)y * (256 * 192);
    float* C = (y == 0) ? Cni : (y == 1) ? Cnj : Cnode;
    const float* bias = (y == 2) ? bnode_l : nullptr;

    mma_tile_to_stage(smem, A, Wp, row0, N_NODES, tid, w, lane);
    __syncthreads();

    float* stage = (float*)smem;
    int rows = min(128, N_NODES - row0);
    for (int u = tid; u < rows * 64; u += 512) {
        int m2 = u >> 6, c4 = (u & 63) * 4;
        float4 v = *(float4*)(stage + m2 * 260 + c4);
        if (bias) {
            float4 bb = *(const float4*)(bias + c4);
            v.x += bb.x; v.y += bb.y; v.z += bb.z; v.w += bb.w;
        }
        *(float4*)(C + (size_t)(row0 + m2) * 256 + c4) = v;
    }
}

// ======== fused edge GEMM + edge_pass1 ========
// f_out = fs@Wfij (tile) + hni[src] + hnj[dst] + bias_e; emits scores (+segmax)
// and next-layer f (in-place into g_fs).
__global__ void __launch_bounds__(512, 1)
gemm_edge(const __nv_bfloat16* __restrict__ A, const __nv_bfloat16* __restrict__ Wp,
          const float* __restrict__ bias_e_l, const float* __restrict__ attn_l,
          const int* __restrict__ src, const int* __restrict__ dst) {
    extern __shared__ __align__(1024) char smem[];
    const int tid = threadIdx.x, w = tid >> 5, lane = tid & 31;
    const int row0 = blockIdx.x * 128;

    mma_tile_to_stage(smem, A, Wp, row0, N_EDGES, tid, w, lane);

    // aux smem (placed after the 128x260 float stage = 133120 B)
    int* sSrc = (int*)(smem + 133120);
    int* sDst = (int*)(smem + 133632);
    float* sAttn = (float*)(smem + 134144);
    float* sBias = (float*)(smem + 135168);
    if (tid < 128) {
        int e = row0 + tid;
        sSrc[tid] = (e < N_EDGES) ? src[e] : 0;
        sDst[tid] = (e < N_EDGES) ? dst[e] : 0;
    } else if (tid < 384) {
        sAttn[tid - 128] = attn_l[tid - 128];
    } else {
        int c = (tid - 384) * 2;
        sBias[c] = bias_e_l[c];
        sBias[c + 1] = bias_e_l[c + 1];
    }
    __syncthreads();

    float* stage = (float*)smem;
    // each warp processes 8 edges
    for (int k = 0; k < 8; k++) {
        int el = w * 8 + k;
        int e = row0 + el;
        if (e >= N_EDGES) break;
        int s = sSrc[el], d = sDst[el];
        const float* pni = g_hni + (size_t)s * HC;
        const float* pnj = g_hnj + (size_t)d * HC;

        float v[8];
#pragma unroll
        for (int j = 0; j < 8; j++) {
            int c = lane + 32 * j;
            v[j] = stage[el * 260 + c] + pni[c] + pnj[c] + sBias[c];
        }
        float p[NHEAD];
#pragma unroll
        for (int h = 0; h < NHEAD; h++) {
            float a0 = sAttn[h * 64 + lane];
            float a1 = sAttn[h * 64 + lane + 32];
            float x0 = v[2 * h], x1 = v[2 * h + 1];
            float l0 = x0 > 0.f ? x0 : 0.01f * x0;
            float l1 = x1 > 0.f ? x1 : 0.01f * x1;
            p[h] = l0 * a0 + l1 * a1;
        }
#pragma unroll
        for (int o = 16; o; o >>= 1) {
#pragma unroll
            for (int h = 0; h < NHEAD; h++)
                p[h] += __shfl_xor_sync(0xffffffffu, p[h], o);
        }
        if (lane < NHEAD) {
            g_score[e * NHEAD + lane] = p[lane];
            atomicMax(&g_smax[(size_t)d * NHEAD + lane], fenc(p[lane]));
        }
        // next-layer f (in-place: this CTA owns row e exclusively)
        float m0 = 0.25f * (v[0] + v[2] + v[4] + v[6]);
        float m1 = 0.25f * (v[1] + v[3] + v[5] + v[7]);
        float sum = warp_sum(m0 + m1);
        float sq = warp_sum(m0 * m0 + m1 * m1);
        float mean = sum * (1.f / 64.f);
        float var = sq * (1.f / 64.f) - mean * mean;
        float rs = rsqrtf(var + 1e-5f);
        float f0 = eluf((m0 - mean) * rs);
        float f1 = eluf((m1 - mean) * rs);
        __nv_bfloat16 h0 = __float2bfloat16(f0);
        __nv_bfloat16 h1 = __float2bfloat16(f1);
        size_t b = (size_t)e * 128;
        g_fs[b + lane] = h0;
        g_fs[b + lane + 32] = h1;
        g_fs[b + 64 + lane] = __float2bfloat16(f0 - __bfloat162float(h0));
        g_fs[b + 96 + lane] = __float2bfloat16(f1 - __bfloat162float(h1));
    }
}

// ---------------- fp32 SGEMM (input/output projections), optional split output ----------------
__global__ void gemm64(const float* __restrict__ A, const float* __restrict__ B,
                       const float* __restrict__ bias, float* __restrict__ Cout,
                       __nv_bfloat16* __restrict__ Csplit,
                       int M, int K, int Nt) {
    __shared__ __align__(16) float sAt[65][68];
    __shared__ __align__(16) float sB[65][68];
    const int row0 = blockIdx.x * 64;
    const int col0 = blockIdx.y * 64;
    const int tid = threadIdx.x;

    for (int idx = tid; idx < 64 * K; idx += 256) {
        int r = idx / K, k = idx - r * K;
        sAt[k][r] = (row0 + r < M) ? A[(size_t)(row0 + r) * K + k] : 0.f;
    }
    for (int idx = tid; idx < K * 64; idx += 256) {
        int k = idx >> 6, c = idx & 63;
        sB[k][c] = B[(size_t)k * Nt + col0 + c];
    }
    __syncthreads();

    const int tx = tid & 15, ty = tid >> 4;
    float acc[4][4];
#pragma unroll
    for (int i = 0; i < 4; i++)
#pragma unroll
        for (int j = 0; j < 4; j++) acc[i][j] = 0.f;

#pragma unroll 4
    for (int k = 0; k < K; k++) {
        float4 a4 = *(const float4*)&sAt[k][ty * 4];
        float4 b4 = *(const float4*)&sB[k][tx * 4];
        float aa[4] = {a4.x, a4.y, a4.z, a4.w};
        float bb[4] = {b4.x, b4.y, b4.z, b4.w};
#pragma unroll
        for (int i = 0; i < 4; i++)
#pragma unroll
            for (int j = 0; j < 4; j++) acc[i][j] += aa[i] * bb[j];
    }
    float bv[4];
#pragma unroll
    for (int j = 0; j < 4; j++) bv[j] = bias ? bias[col0 + tx * 4 + j] : 0.f;
#pragma unroll
    for (int i = 0; i < 4; i++) {
        int r = row0 + ty * 4 + i;
        if (r < M) {
#pragma unroll
            for (int j = 0; j < 4; j++) {
                float val = acc[i][j] + bv[j];
                int col = col0 + tx * 4 + j;
                if (Cout) Cout[(size_t)r * Nt + col] = val;
                if (Csplit) {
                    __nv_bfloat16 hi = __float2bfloat16(val);
                    Csplit[(size_t)r * 128 + col] = hi;
                    Csplit[(size_t)r * 128 + 64 + col] = __float2bfloat16(val - __bfloat162float(hi));
                }
            }
        }
    }
}

// ---------------- weight prep ----------------
__global__ void prep_weight(const float* __restrict__ W, __nv_bfloat16* __restrict__ Wp) {
    int idx = blockIdx.x * blockDim.x + threadIdx.x;
    if (idx >= 256 * 192) return;
    int n = idx / 192, kk = idx - n * 192;
    int k = kk & 63;
    float v = W[(size_t)k * 256 + n];
    __nv_bfloat16 hi = __float2bfloat16(v);
    __nv_bfloat16 out = hi;
    if (kk >= 64 && kk < 128) out = __float2bfloat16(v - __bfloat162float(hi));
    Wp[idx] = out;
}

// ---------------- per-layer init ----------------
__global__ void init_layer() {
    int idx = blockIdx.x * blockDim.x + threadIdx.x;
    if (idx < N_NODES * CH) g_hacc[idx] = 0.f;
    if (idx < N_NODES * NHEAD) {
        g_denom[idx] = 0.f;
        g_smax[idx] = 0x007fffffu;
    }
}

// ---------------- edge pass 2 ----------------
__global__ void edge_pass2(const int* __restrict__ dst) {
    int idx = blockIdx.x * blockDim.x + threadIdx.x;
    if (idx >= N_EDGES * NHEAD) return;
    int e = idx >> 2, h = idx & 3;
    int d = dst[e];
    float mx = fdec(g_smax[(size_t)d * NHEAD + h]);
    float w = __expf(g_score[idx] - mx);
    g_score[idx] = w;
    atomicAdd(&g_denom[(size_t)d * NHEAD + h], w);
}

// ---------------- edge pass 3 ----------------
__global__ void edge_pass3(const int* __restrict__ src, const int* __restrict__ dst) {
    int e = (blockIdx.x * blockDim.x + threadIdx.x) >> 5;
    if (e >= N_EDGES) return;
    int lane = threadIdx.x & 31;
    int s = src[e], d = dst[e];
    float a0 = g_score[e * NHEAD + 0] / g_denom[(size_t)d * NHEAD + 0];
    float a1 = g_score[e * NHEAD + 1] / g_denom[(size_t)d * NHEAD + 1];
    float a2 = g_score[e * NHEAD + 2] / g_denom[(size_t)d * NHEAD + 2];
    float a3 = g_score[e * NHEAD + 3] / g_denom[(size_t)d * NHEAD + 3];
    const float* hp = g_hproj + (size_t)s * HC;
    float acc0 = 0.25f * (hp[lane] * a0 + hp[64 + lane] * a1 +
                          hp[128 + lane] * a2 + hp[192 + lane] * a3);
    float acc1 = 0.25f * (hp[32 + lane] * a0 + hp[96 + lane] * a1 +
                          hp[160 + lane] * a2 + hp[224 + lane] * a3);
    atomicAdd(&g_hacc[(size_t)d * CH + lane], acc0);
    atomicAdd(&g_hacc[(size_t)d * CH + lane + 32], acc1);
}

// ---------------- node norm ----------------
__global__ void node_norm() {
    int n = (blockIdx.x * blockDim.x + threadIdx.x) >> 5;
    if (n >= N_NODES) return;
    int lane = threadIdx.x & 31;
    float m0 = g_hacc[(size_t)n * CH + lane];
    float m1 = g_hacc[(size_t)n * CH + lane + 32];
    float sum = warp_sum(m0 + m1);
    float sq = warp_sum(m0 * m0 + m1 * m1);
    float mean = sum * (1.f / 64.f);
    float var = sq * (1.f / 64.f) - mean * mean;
    float rs = rsqrtf(var + 1e-5f);
    float h0 = eluf((m0 - mean) * rs);
    float h1 = eluf((m1 - mean) * rs);
    g_h[(size_t)n * CH + lane] = h0;
    g_h[(size_t)n * CH + lane + 32] = h1;
    __nv_bfloat16 b0 = __float2bfloat16(h0);
    __nv_bfloat16 b1 = __float2bfloat16(h1);
    size_t b = (size_t)n * 128;
    g_hs[b + lane] = b0;
    g_hs[b + lane + 32] = b1;
    g_hs[b + 64 + lane] = __float2bfloat16(h0 - __bfloat162float(b0));
    g_hs[b + 96 + lane] = __float2bfloat16(h1 - __bfloat162float(b1));
}

// ---------------- launcher ----------------
extern "C" void kernel_launch(void* const* d_in, const int* in_sizes, int n_in,
                              void* d_out, int out_size) {
    const float* x = (const float*)d_in[0];
    const float* efeat = (const float*)d_in[1];
    const int* src = (const int*)d_in[2];
    const int* dst = (const int*)d_in[3];
    const float* Wn0 = (const float*)d_in[4];
    const float* bn0 = (const float*)d_in[5];
    const float* We0 = (const float*)d_in[6];
    const float* be0 = (const float*)d_in[7];
    const float* Wnode = (const float*)d_in[8];
    const float* bnode = (const float*)d_in[9];
    const float* Wni = (const float*)d_in[10];
    const float* Wnj = (const float*)d_in[11];
    const float* Wfij = (const float*)d_in[12];
    const float* attn = (const float*)d_in[13];
    const float* bias_e = (const float*)d_in[14];
    const float* Wf = (const float*)d_in[15];
    const float* bf = (const float*)d_in[16];

    float *ph, *phni, *phnj, *phproj;
    __nv_bfloat16 *phs, *pfs, *pwp;
    cudaGetSymbolAddress((void**)&ph, g_h);
    cudaGetSymbolAddress((void**)&phni, g_hni);
    cudaGetSymbolAddress((void**)&phnj, g_hnj);
    cudaGetSymbolAddress((void**)&phproj, g_hproj);
    cudaGetSymbolAddress((void**)&phs, g_hs);
    cudaGetSymbolAddress((void**)&pfs, g_fs);
    cudaGetSymbolAddress((void**)&pwp, g_wprep);

    cudaFuncSetAttribute(gemm_node3, cudaFuncAttributeMaxDynamicSharedMemorySize, MM_SMEM);
    cudaFuncSetAttribute(gemm_edge, cudaFuncAttributeMaxDynamicSharedMemorySize, MM_SMEM);

    const dim3 blk(256);
    const int NB_N = (N_NODES + 63) / 64;
    const int NB_E = (N_EDGES + 63) / 64;
    const int TB_N = (N_NODES + 127) / 128;   // 157
    const int TB_E = (N_EDGES + 127) / 128;   // 1563
    const int WPSZ = 256 * 192;

    // weight prep: layout per layer [ni, nj, node, fij]
    for (int l = 0; l < 2; l++) {
        prep_weight<<<192, blk>>>(Wni + (size_t)l * 64 * 256, pwp + (size_t)(l * 4 + 0) * WPSZ);
        prep_weight<<<192, blk>>>(Wnj + (size_t)l * 64 * 256, pwp + (size_t)(l * 4 + 1) * WPSZ);
        prep_weight<<<192, blk>>>(Wnode + (size_t)l * 64 * 256, pwp + (size_t)(l * 4 + 2) * WPSZ);
        prep_weight<<<192, blk>>>(Wfij + (size_t)l * 64 * 256, pwp + (size_t)(l * 4 + 3) * WPSZ);
    }

    // input projections (fp32 -> split bf16 directly)
    gemm64<<<dim3(NB_N, 1), blk>>>(x, Wn0, bn0, nullptr, phs, N_NODES, 65, 64);
    gemm64<<<dim3(NB_E, 1), blk>>>(efeat, We0, be0, nullptr, pfs, N_EDGES, 15, 64);

    for (int l = 0; l < 2; l++) {
        const float* bnode_l = bnode + (size_t)l * 256;
        const float* bias_e_l = bias_e + (size_t)l * 256;
        const float* attn_l = attn + (size_t)l * 256;

        init_layer<<<(N_NODES * CH + 255) / 256, blk>>>();
        gemm_node3<<<dim3(TB_N, 3), 512, MM_SMEM>>>(phs, pwp + (size_t)(l * 4) * WPSZ,
                                                    bnode_l, phni, phnj, phproj);
        gemm_edge<<<TB_E, 512, MM_SMEM>>>(pfs, pwp + (size_t)(l * 4 + 3) * WPSZ,
                                          bias_e_l, attn_l, src, dst);
        edge_pass2<<<(N_EDGES * NHEAD + 255) / 256, blk>>>(dst);
        edge_pass3<<<(N_EDGES * 32 + 255) / 256, blk>>>(src, dst);
        node_norm<<<(N_NODES * 32 + 255) / 256, blk>>>();
    }

    gemm64<<<dim3(NB_N, 1), blk>>>(ph, Wf, bf, (float*)d_out, nullptr, N_NODES, 64, 64);
}

// round 5
// speedup vs baseline: 1.5430x; 1.1853x over previous
#include <cuda_runtime.h>
#include <cuda_bf16.h>
#include <math.h>
#include <stdint.h>

#define N_NODES 20000
#define N_EDGES 200000
#define CH 64
#define HC 256
#define NHEAD 4

// ---------------- scratch ----------------
__device__ __align__(256) float    g_h[N_NODES * CH];
__device__ __align__(256) __nv_bfloat16 g_hs[N_NODES * 128];
__device__ __align__(256) __nv_bfloat16 g_fs[N_EDGES * 128];
__device__ __align__(256) __nv_bfloat16 g_wprep[8 * 256 * 192];
__device__ __align__(256) float    g_hni[N_NODES * HC];
__device__ __align__(256) float    g_hnj[N_NODES * HC];
__device__ __align__(256) float    g_hproj[N_NODES * HC];
__device__ __align__(256) float    g_score[N_EDGES * NHEAD];
__device__ __align__(256) float    g_denom[N_NODES * NHEAD];
__device__ __align__(256) unsigned g_smax[N_NODES * NHEAD];
__device__ __align__(256) float    g_hacc[N_NODES * CH];

// ---------------- helpers ----------------
__device__ __forceinline__ uint32_t smem_u32(const void* p) {
    uint32_t a;
    asm("{ .reg .u64 t; cvta.to.shared.u64 t, %1; cvt.u32.u64 %0, t; }" : "=r"(a) : "l"(p));
    return a;
}
__device__ __forceinline__ unsigned fenc(float f) {
    unsigned u = __float_as_uint(f);
    return (u & 0x80000000u) ? ~u : (u | 0x80000000u);
}
__device__ __forceinline__ float fdec(unsigned u) {
    return (u & 0x80000000u) ? __uint_as_float(u ^ 0x80000000u) : __uint_as_float(~u);
}
__device__ __forceinline__ float eluf(float x) { return x > 0.f ? x : expm1f(x); }
__device__ __forceinline__ float warp_sum(float v) {
#pragma unroll
    for (int o = 16; o; o >>= 1) v += __shfl_xor_sync(0xffffffffu, v, o);
    return v;
}
__device__ __forceinline__ void ldm_x4(uint32_t* r, uint32_t addr) {
    asm volatile("ldmatrix.sync.aligned.m8n8.x4.shared.b16 {%0,%1,%2,%3}, [%4];"
                 : "=r"(r[0]), "=r"(r[1]), "=r"(r[2]), "=r"(r[3]) : "r"(addr));
}
__device__ __forceinline__ void mma_bf16(float* d, const uint32_t* a, const uint32_t* b) {
    asm volatile("mma.sync.aligned.m16n8k16.row.col.f32.bf16.bf16.f32 "
                 "{%0,%1,%2,%3}, {%4,%5,%6,%7}, {%8,%9}, {%0,%1,%2,%3};"
                 : "+f"(d[0]), "+f"(d[1]), "+f"(d[2]), "+f"(d[3])
                 : "r"(a[0]), "r"(a[1]), "r"(a[2]), "r"(a[3]), "r"(b[0]), "r"(b[1]));
}

#define MM_SMEM 153600
#define SMB_OFF 51200

// ======== core mma tile: cp.async fills, 12 k-steps, stage C in smem ========
__device__ __forceinline__ void mma_tile_to_stage(
    char* smem, const __nv_bfloat16* __restrict__ A, const __nv_bfloat16* __restrict__ Wp,
    int row0, int M, int tid, int w, int lane) {
    __nv_bfloat16* smA = (__nv_bfloat16*)smem;
    __nv_bfloat16* smB = (__nv_bfloat16*)(smem + SMB_OFF);

    // A': 128 rows x 192 k' ([hi|hi|lo]), pad stride 200 elems
    for (int u = tid; u < 3072; u += 512) {
        int m = u / 24, k0 = (u - m * 24) * 8;
        int sc = (k0 & 63) + (k0 >= 128 ? 64 : 0);
        int mm = row0 + m < M ? row0 + m : M - 1;
        int bytes = (row0 + m < M) ? 16 : 0;
        const void* gp = A + (size_t)mm * 128 + sc;
        uint32_t sa = smem_u32(smA + m * 200 + k0);
        asm volatile("cp.async.cg.shared.global [%0], [%1], 16, %2;"
                     :: "r"(sa), "l"(gp), "r"(bytes));
    }
    // B: [n=256][k'=192], pad stride 200
    for (int u = tid; u < 6144; u += 512) {
        int n = u / 24, k0 = (u - n * 24) * 8;
        uint32_t sa = smem_u32(smB + n * 200 + k0);
        asm volatile("cp.async.cg.shared.global [%0], [%1], 16;"
                     :: "r"(sa), "l"(Wp + (size_t)n * 192 + k0));
    }
    asm volatile("cp.async.commit_group;");
    asm volatile("cp.async.wait_group 0;" ::: "memory");
    __syncthreads();

    const int mw = (w >> 3) * 64;
    const int nw = (w & 7) * 32;
    const int g = lane >> 3, r = lane & 7;

    float acc[4][4][4];
#pragma unroll
    for (int i = 0; i < 4; i++)
#pragma unroll
        for (int j = 0; j < 4; j++)
#pragma unroll
            for (int q = 0; q < 4; q++) acc[i][j][q] = 0.f;

    uint32_t aAddr = smem_u32(smA) + ((mw + (g & 1) * 8 + r) * 200 + (g >> 1) * 8) * 2;
    uint32_t bAddr = smem_u32(smB) + ((nw + (g >> 1) * 8 + r) * 200 + (g & 1) * 8) * 2;

    for (int ks = 0; ks < 12; ks++) {
        uint32_t af[4][4], bf[2][4];
#pragma unroll
        for (int i = 0; i < 4; i++) ldm_x4(af[i], aAddr + i * 6400);
#pragma unroll
        for (int p = 0; p < 2; p++) ldm_x4(bf[p], bAddr + p * 6400);
#pragma unroll
        for (int i = 0; i < 4; i++)
#pragma unroll
            for (int j = 0; j < 4; j++)
                mma_bf16(acc[i][j], af[i], &bf[j >> 1][(j & 1) * 2]);
        aAddr += 32;
        bAddr += 32;
    }

    __syncthreads();
    float* stage = (float*)smem;
#pragma unroll
    for (int i = 0; i < 4; i++)
#pragma unroll
        for (int j = 0; j < 4; j++) {
            int m = mw + i * 16 + (lane >> 2);
            int n = nw + j * 8 + (lane & 3) * 2;
            stage[m * 260 + n] = acc[i][j][0];
            stage[m * 260 + n + 1] = acc[i][j][1];
            stage[(m + 8) * 260 + n] = acc[i][j][2];
            stage[(m + 8) * 260 + n + 1] = acc[i][j][3];
        }
}

// ======== node GEMMs: 3 weights in one launch ========
__global__ void __launch_bounds__(512, 1)
gemm_node3(const __nv_bfloat16* __restrict__ A, const __nv_bfloat16* __restrict__ WpBase,
           const float* __restrict__ bnode_l,
           float* __restrict__ Cni, float* __restrict__ Cnj, float* __restrict__ Cnode) {
    extern __shared__ __align__(1024) char smem[];
    const int tid = threadIdx.x, w = tid >> 5, lane = tid & 31;
    const int row0 = blockIdx.x * 128;
    const int y = blockIdx.y;
    const __nv_bfloat16* Wp = WpBase + (size_t)y * (256 * 192);
    float* C = (y == 0) ? Cni : (y == 1) ? Cnj : Cnode;
    const float* bias = (y == 2) ? bnode_l : nullptr;

    mma_tile_to_stage(smem, A, Wp, row0, N_NODES, tid, w, lane);
    __syncthreads();

    float* stage = (float*)smem;
    int rows = min(128, N_NODES - row0);
    for (int u = tid; u < rows * 64; u += 512) {
        int m2 = u >> 6, c4 = (u & 63) * 4;
        float4 v = *(float4*)(stage + m2 * 260 + c4);
        if (bias) {
            float4 bb = *(const float4*)(bias + c4);
            v.x += bb.x; v.y += bb.y; v.z += bb.z; v.w += bb.w;
        }
        *(float4*)(C + (size_t)(row0 + m2) * 256 + c4) = v;
    }
}

// ======== fused edge GEMM + edge_pass1 ========
__global__ void __launch_bounds__(512, 1)
gemm_edge(const __nv_bfloat16* __restrict__ A, const __nv_bfloat16* __restrict__ Wp,
          const float* __restrict__ bias_e_l, const float* __restrict__ attn_l,
          const int* __restrict__ src, const int* __restrict__ dst) {
    extern __shared__ __align__(1024) char smem[];
    const int tid = threadIdx.x, w = tid >> 5, lane = tid & 31;
    const int row0 = blockIdx.x * 128;

    mma_tile_to_stage(smem, A, Wp, row0, N_EDGES, tid, w, lane);

    int* sSrc = (int*)(smem + 133120);
    int* sDst = (int*)(smem + 133632);
    float* sAttn = (float*)(smem + 134144);
    float* sBias = (float*)(smem + 135168);
    if (tid < 128) {
        int e = row0 + tid;
        sSrc[tid] = (e < N_EDGES) ? src[e] : 0;
        sDst[tid] = (e < N_EDGES) ? dst[e] : 0;
    } else if (tid < 384) {
        sAttn[tid - 128] = attn_l[tid - 128];
    } else {
        int c = (tid - 384) * 2;
        sBias[c] = bias_e_l[c];
        sBias[c + 1] = bias_e_l[c + 1];
    }
    __syncthreads();

    float* stage = (float*)smem;
    for (int k = 0; k < 8; k++) {
        int el = w * 8 + k;
        int e = row0 + el;
        if (e >= N_EDGES) break;
        int s = sSrc[el], d = sDst[el];
        const float* pni = g_hni + (size_t)s * HC;
        const float* pnj = g_hnj + (size_t)d * HC;

        float v[8];
#pragma unroll
        for (int j = 0; j < 8; j++) {
            int c = lane + 32 * j;
            v[j] = stage[el * 260 + c] + pni[c] + pnj[c] + sBias[c];
        }
        float p[NHEAD];
#pragma unroll
        for (int h = 0; h < NHEAD; h++) {
            float a0 = sAttn[h * 64 + lane];
            float a1 = sAttn[h * 64 + lane + 32];
            float x0 = v[2 * h], x1 = v[2 * h + 1];
            float l0 = x0 > 0.f ? x0 : 0.01f * x0;
            float l1 = x1 > 0.f ? x1 : 0.01f * x1;
            p[h] = l0 * a0 + l1 * a1;
        }
#pragma unroll
        for (int o = 16; o; o >>= 1) {
#pragma unroll
            for (int h = 0; h < NHEAD; h++)
                p[h] += __shfl_xor_sync(0xffffffffu, p[h], o);
        }
        if (lane < NHEAD) {
            g_score[e * NHEAD + lane] = p[lane];
            atomicMax(&g_smax[(size_t)d * NHEAD + lane], fenc(p[lane]));
        }
        float m0 = 0.25f * (v[0] + v[2] + v[4] + v[6]);
        float m1 = 0.25f * (v[1] + v[3] + v[5] + v[7]);
        float sum = warp_sum(m0 + m1);
        float sq = warp_sum(m0 * m0 + m1 * m1);
        float mean = sum * (1.f / 64.f);
        float var = sq * (1.f / 64.f) - mean * mean;
        float rs = rsqrtf(var + 1e-5f);
        float f0 = eluf((m0 - mean) * rs);
        float f1 = eluf((m1 - mean) * rs);
        __nv_bfloat16 h0 = __float2bfloat16(f0);
        __nv_bfloat16 h1 = __float2bfloat16(f1);
        size_t b = (size_t)e * 128;
        g_fs[b + lane] = h0;
        g_fs[b + lane + 32] = h1;
        g_fs[b + 64 + lane] = __float2bfloat16(f0 - __bfloat162float(h0));
        g_fs[b + 96 + lane] = __float2bfloat16(f1 - __bfloat162float(h1));
    }
}

// ---------------- fp32 SGEMM (input/output projections) ----------------
__global__ void gemm64(const float* __restrict__ A, const float* __restrict__ B,
                       const float* __restrict__ bias, float* __restrict__ Cout,
                       __nv_bfloat16* __restrict__ Csplit,
                       int M, int K, int Nt) {
    __shared__ __align__(16) float sAt[65][68];
    __shared__ __align__(16) float sB[65][68];
    const int row0 = blockIdx.x * 64;
    const int col0 = blockIdx.y * 64;
    const int tid = threadIdx.x;

    for (int idx = tid; idx < 64 * K; idx += 256) {
        int r = idx / K, k = idx - r * K;
        sAt[k][r] = (row0 + r < M) ? A[(size_t)(row0 + r) * K + k] : 0.f;
    }
    for (int idx = tid; idx < K * 64; idx += 256) {
        int k = idx >> 6, c = idx & 63;
        sB[k][c] = B[(size_t)k * Nt + col0 + c];
    }
    __syncthreads();

    const int tx = tid & 15, ty = tid >> 4;
    float acc[4][4];
#pragma unroll
    for (int i = 0; i < 4; i++)
#pragma unroll
        for (int j = 0; j < 4; j++) acc[i][j] = 0.f;

#pragma unroll 4
    for (int k = 0; k < K; k++) {
        float4 a4 = *(const float4*)&sAt[k][ty * 4];
        float4 b4 = *(const float4*)&sB[k][tx * 4];
        float aa[4] = {a4.x, a4.y, a4.z, a4.w};
        float bb[4] = {b4.x, b4.y, b4.z, b4.w};
#pragma unroll
        for (int i = 0; i < 4; i++)
#pragma unroll
            for (int j = 0; j < 4; j++) acc[i][j] += aa[i] * bb[j];
    }
    float bv[4];
#pragma unroll
    for (int j = 0; j < 4; j++) bv[j] = bias ? bias[col0 + tx * 4 + j] : 0.f;
#pragma unroll
    for (int i = 0; i < 4; i++) {
        int r = row0 + ty * 4 + i;
        if (r < M) {
#pragma unroll
            for (int j = 0; j < 4; j++) {
                float val = acc[i][j] + bv[j];
                int col = col0 + tx * 4 + j;
                if (Cout) Cout[(size_t)r * Nt + col] = val;
                if (Csplit) {
                    __nv_bfloat16 hi = __float2bfloat16(val);
                    Csplit[(size_t)r * 128 + col] = hi;
                    Csplit[(size_t)r * 128 + 64 + col] = __float2bfloat16(val - __bfloat162float(hi));
                }
            }
        }
    }
}

// ---------------- weight prep: ALL 8 matrices in one launch ----------------
__global__ void prep_all(const float* __restrict__ Wni, const float* __restrict__ Wnj,
                         const float* __restrict__ Wnode, const float* __restrict__ Wfij) {
    int mat = blockIdx.x / 192;
    int idx = (blockIdx.x % 192) * 256 + threadIdx.x;  // 0..49151
    int l = mat >> 2, type = mat & 3;
    const float* W = (type == 0 ? Wni : type == 1 ? Wnj : type == 2 ? Wnode : Wfij)
                     + (size_t)l * 64 * 256;
    __nv_bfloat16* Wp = g_wprep + (size_t)mat * (256 * 192);
    int n = idx / 192, kk = idx - n * 192;
    int k = kk & 63;
    float v = W[(size_t)k * 256 + n];
    __nv_bfloat16 hi = __float2bfloat16(v);
    __nv_bfloat16 out = hi;
    if (kk >= 64 && kk < 128) out = __float2bfloat16(v - __bfloat162float(hi));
    Wp[idx] = out;
}

// ---------------- one-time init (layer 0 accumulators) ----------------
__global__ void init_layer() {
    int idx = blockIdx.x * blockDim.x + threadIdx.x;
    if (idx < N_NODES * CH) g_hacc[idx] = 0.f;
    if (idx < N_NODES * NHEAD) {
        g_denom[idx] = 0.f;
        g_smax[idx] = 0x007fffffu;
    }
}

// ---------------- edge pass 2: one edge per thread, float4 ----------------
__global__ void edge_pass2(const int* __restrict__ dst) {
    int e = blockIdx.x * blockDim.x + threadIdx.x;
    if (e >= N_EDGES) return;
    int d = dst[e];
    float4 sc = *(float4*)(g_score + (size_t)e * 4);
    const unsigned* sm = g_smax + (size_t)d * 4;
    float4 wv;
    wv.x = __expf(sc.x - fdec(sm[0]));
    wv.y = __expf(sc.y - fdec(sm[1]));
    wv.z = __expf(sc.z - fdec(sm[2]));
    wv.w = __expf(sc.w - fdec(sm[3]));
    *(float4*)(g_score + (size_t)e * 4) = wv;
    float* dn = g_denom + (size_t)d * 4;
    atomicAdd(dn + 0, wv.x);
    atomicAdd(dn + 1, wv.y);
    atomicAdd(dn + 2, wv.z);
    atomicAdd(dn + 3, wv.w);
}

// ---------------- edge pass 3 ----------------
__global__ void edge_pass3(const int* __restrict__ src, const int* __restrict__ dst) {
    int e = (blockIdx.x * blockDim.x + threadIdx.x) >> 5;
    if (e >= N_EDGES) return;
    int lane = threadIdx.x & 31;
    int s = src[e], d = dst[e];
    float a0 = g_score[e * NHEAD + 0] / g_denom[(size_t)d * NHEAD + 0];
    float a1 = g_score[e * NHEAD + 1] / g_denom[(size_t)d * NHEAD + 1];
    float a2 = g_score[e * NHEAD + 2] / g_denom[(size_t)d * NHEAD + 2];
    float a3 = g_score[e * NHEAD + 3] / g_denom[(size_t)d * NHEAD + 3];
    const float* hp = g_hproj + (size_t)s * HC;
    float acc0 = 0.25f * (hp[lane] * a0 + hp[64 + lane] * a1 +
                          hp[128 + lane] * a2 + hp[192 + lane] * a3);
    float acc1 = 0.25f * (hp[32 + lane] * a0 + hp[96 + lane] * a1 +
                          hp[160 + lane] * a2 + hp[224 + lane] * a3);
    atomicAdd(&g_hacc[(size_t)d * CH + lane], acc0);
    atomicAdd(&g_hacc[(size_t)d * CH + lane + 32], acc1);
}

// ---------------- node norm (+ re-init accumulators for next layer) ----------------
__global__ void node_norm() {
    int n = (blockIdx.x * blockDim.x + threadIdx.x) >> 5;
    if (n >= N_NODES) return;
    int lane = threadIdx.x & 31;
    float m0 = g_hacc[(size_t)n * CH + lane];
    float m1 = g_hacc[(size_t)n * CH + lane + 32];
    float sum = warp_sum(m0 + m1);
    float sq = warp_sum(m0 * m0 + m1 * m1);
    float mean = sum * (1.f / 64.f);
    float var = sq * (1.f / 64.f) - mean * mean;
    float rs = rsqrtf(var + 1e-5f);
    float h0 = eluf((m0 - mean) * rs);
    float h1 = eluf((m1 - mean) * rs);
    g_h[(size_t)n * CH + lane] = h0;
    g_h[(size_t)n * CH + lane + 32] = h1;
    __nv_bfloat16 b0 = __float2bfloat16(h0);
    __nv_bfloat16 b1 = __float2bfloat16(h1);
    size_t b = (size_t)n * 128;
    g_hs[b + lane] = b0;
    g_hs[b + lane + 32] = b1;
    g_hs[b + 64 + lane] = __float2bfloat16(h0 - __bfloat162float(b0));
    g_hs[b + 96 + lane] = __float2bfloat16(h1 - __bfloat162float(b1));
    // re-init accumulators for the next layer
    g_hacc[(size_t)n * CH + lane] = 0.f;
    g_hacc[(size_t)n * CH + lane + 32] = 0.f;
    if (lane < NHEAD) {
        g_denom[(size_t)n * NHEAD + lane] = 0.f;
        g_smax[(size_t)n * NHEAD + lane] = 0x007fffffu;
    }
}

// ---------------- launcher ----------------
extern "C" void kernel_launch(void* const* d_in, const int* in_sizes, int n_in,
                              void* d_out, int out_size) {
    const float* x = (const float*)d_in[0];
    const float* efeat = (const float*)d_in[1];
    const int* src = (const int*)d_in[2];
    const int* dst = (const int*)d_in[3];
    const float* Wn0 = (const float*)d_in[4];
    const float* bn0 = (const float*)d_in[5];
    const float* We0 = (const float*)d_in[6];
    const float* be0 = (const float*)d_in[7];
    const float* Wnode = (const float*)d_in[8];
    const float* bnode = (const float*)d_in[9];
    const float* Wni = (const float*)d_in[10];
    const float* Wnj = (const float*)d_in[11];
    const float* Wfij = (const float*)d_in[12];
    const float* attn = (const float*)d_in[13];
    const float* bias_e = (const float*)d_in[14];
    const float* Wf = (const float*)d_in[15];
    const float* bf = (const float*)d_in[16];

    float *ph, *phni, *phnj, *phproj;
    __nv_bfloat16 *phs, *pfs, *pwp;
    cudaGetSymbolAddress((void**)&ph, g_h);
    cudaGetSymbolAddress((void**)&phni, g_hni);
    cudaGetSymbolAddress((void**)&phnj, g_hnj);
    cudaGetSymbolAddress((void**)&phproj, g_hproj);
    cudaGetSymbolAddress((void**)&phs, g_hs);
    cudaGetSymbolAddress((void**)&pfs, g_fs);
    cudaGetSymbolAddress((void**)&pwp, g_wprep);

    cudaFuncSetAttribute(gemm_node3, cudaFuncAttributeMaxDynamicSharedMemorySize, MM_SMEM);
    cudaFuncSetAttribute(gemm_edge, cudaFuncAttributeMaxDynamicSharedMemorySize, MM_SMEM);

    const dim3 blk(256);
    const int NB_N = (N_NODES + 63) / 64;
    const int NB_E = (N_EDGES + 63) / 64;
    const int TB_N = (N_NODES + 127) / 128;   // 157
    const int TB_E = (N_EDGES + 127) / 128;   // 1563
    const int WPSZ = 256 * 192;

    // launch 0: all weight prep
    prep_all<<<8 * 192, blk>>>(Wni, Wnj, Wnode, Wfij);
    // launches 1-2: input projections (fp32 -> split bf16)
    gemm64<<<dim3(NB_N, 1), blk>>>(x, Wn0, bn0, nullptr, phs, N_NODES, 65, 64);
    gemm64<<<dim3(NB_E, 1), blk>>>(efeat, We0, be0, nullptr, pfs, N_EDGES, 15, 64);
    // launch 3: init accumulators for layer 0
    init_layer<<<(N_NODES * CH + 255) / 256, blk>>>();

    for (int l = 0; l < 2; l++) {
        const float* bnode_l = bnode + (size_t)l * 256;
        const float* bias_e_l = bias_e + (size_t)l * 256;
        const float* attn_l = attn + (size_t)l * 256;

        // launch 4 (l=0): node GEMMs; launch 5 (l=0): gemm_edge  <- ncu target
        gemm_node3<<<dim3(TB_N, 3), 512, MM_SMEM>>>(phs, pwp + (size_t)(l * 4) * WPSZ,
                                                    bnode_l, phni, phnj, phproj);
        gemm_edge<<<TB_E, 512, MM_SMEM>>>(pfs, pwp + (size_t)(l * 4 + 3) * WPSZ,
                                          bias_e_l, attn_l, src, dst);
        edge_pass2<<<(N_EDGES + 255) / 256, blk>>>(dst);
        edge_pass3<<<(N_EDGES * 32 + 255) / 256, blk>>>(src, dst);
        node_norm<<<(N_NODES * 32 + 255) / 256, blk>>>();
    }

    gemm64<<<dim3(NB_N, 1), blk>>>(ph, Wf, bf, (float*)d_out, nullptr, N_NODES, 64, 64);
}

// round 6
// speedup vs baseline: 1.5874x; 1.0287x over previous
#include <cuda_runtime.h>
#include <cuda_bf16.h>
#include <math.h>
#include <stdint.h>

#define N_NODES 20000
#define N_EDGES 200000
#define CH 64
#define HC 256
#define NHEAD 4

// ---------------- scratch ----------------
__device__ __align__(256) float    g_h[N_NODES * CH];
__device__ __align__(256) __nv_bfloat16 g_hs[N_NODES * 128];
__device__ __align__(256) __nv_bfloat16 g_fs[N_EDGES * 128];
__device__ __align__(256) __nv_bfloat16 g_wprep[8 * 256 * 192];
__device__ __align__(256) float    g_hni[N_NODES * HC];
__device__ __align__(256) float    g_hnj[N_NODES * HC];
__device__ __align__(256) float    g_hproj[N_NODES * HC];
__device__ __align__(256) float    g_score[N_EDGES * NHEAD];
// CSR by dst
__device__ __align__(256) int g_deg[N_NODES];
__device__ __align__(256) int g_off[N_NODES + 1];
__device__ __align__(256) int g_cursor[N_NODES];
__device__ __align__(256) int g_eidx[N_EDGES];

// ---------------- helpers ----------------
__device__ __forceinline__ uint32_t smem_u32(const void* p) {
    uint32_t a;
    asm("{ .reg .u64 t; cvta.to.shared.u64 t, %1; cvt.u32.u64 %0, t; }" : "=r"(a) : "l"(p));
    return a;
}
__device__ __forceinline__ float eluf(float x) { return x > 0.f ? x : expm1f(x); }
__device__ __forceinline__ float warp_sum(float v) {
#pragma unroll
    for (int o = 16; o; o >>= 1) v += __shfl_xor_sync(0xffffffffu, v, o);
    return v;
}
__device__ __forceinline__ float warp_max(float v) {
#pragma unroll
    for (int o = 16; o; o >>= 1) v = fmaxf(v, __shfl_xor_sync(0xffffffffu, v, o));
    return v;
}
__device__ __forceinline__ void ldm_x4(uint32_t* r, uint32_t addr) {
    asm volatile("ldmatrix.sync.aligned.m8n8.x4.shared.b16 {%0,%1,%2,%3}, [%4];"
                 : "=r"(r[0]), "=r"(r[1]), "=r"(r[2]), "=r"(r[3]) : "r"(addr));
}
__device__ __forceinline__ void mma_bf16(float* d, const uint32_t* a, const uint32_t* b) {
    asm volatile("mma.sync.aligned.m16n8k16.row.col.f32.bf16.bf16.f32 "
                 "{%0,%1,%2,%3}, {%4,%5,%6,%7}, {%8,%9}, {%0,%1,%2,%3};"
                 : "+f"(d[0]), "+f"(d[1]), "+f"(d[2]), "+f"(d[3])
                 : "r"(a[0]), "r"(a[1]), "r"(a[2]), "r"(a[3]), "r"(b[0]), "r"(b[1]));
}

#define MM_SMEM 153600
#define SMB_OFF 51200

// ======== core mma tile ========
__device__ __forceinline__ void mma_tile_to_stage(
    char* smem, const __nv_bfloat16* __restrict__ A, const __nv_bfloat16* __restrict__ Wp,
    int row0, int M, int tid, int w, int lane) {
    __nv_bfloat16* smA = (__nv_bfloat16*)smem;
    __nv_bfloat16* smB = (__nv_bfloat16*)(smem + SMB_OFF);

    for (int u = tid; u < 3072; u += 512) {
        int m = u / 24, k0 = (u - m * 24) * 8;
        int sc = (k0 & 63) + (k0 >= 128 ? 64 : 0);
        int mm = row0 + m < M ? row0 + m : M - 1;
        int bytes = (row0 + m < M) ? 16 : 0;
        const void* gp = A + (size_t)mm * 128 + sc;
        uint32_t sa = smem_u32(smA + m * 200 + k0);
        asm volatile("cp.async.cg.shared.global [%0], [%1], 16, %2;"
                     :: "r"(sa), "l"(gp), "r"(bytes));
    }
    for (int u = tid; u < 6144; u += 512) {
        int n = u / 24, k0 = (u - n * 24) * 8;
        uint32_t sa = smem_u32(smB + n * 200 + k0);
        asm volatile("cp.async.cg.shared.global [%0], [%1], 16;"
                     :: "r"(sa), "l"(Wp + (size_t)n * 192 + k0));
    }
    asm volatile("cp.async.commit_group;");
    asm volatile("cp.async.wait_group 0;" ::: "memory");
    __syncthreads();

    const int mw = (w >> 3) * 64;
    const int nw = (w & 7) * 32;
    const int g = lane >> 3, r = lane & 7;

    float acc[4][4][4];
#pragma unroll
    for (int i = 0; i < 4; i++)
#pragma unroll
        for (int j = 0; j < 4; j++)
#pragma unroll
            for (int q = 0; q < 4; q++) acc[i][j][q] = 0.f;

    uint32_t aAddr = smem_u32(smA) + ((mw + (g & 1) * 8 + r) * 200 + (g >> 1) * 8) * 2;
    uint32_t bAddr = smem_u32(smB) + ((nw + (g >> 1) * 8 + r) * 200 + (g & 1) * 8) * 2;

    for (int ks = 0; ks < 12; ks++) {
        uint32_t af[4][4], bf[2][4];
#pragma unroll
        for (int i = 0; i < 4; i++) ldm_x4(af[i], aAddr + i * 6400);
#pragma unroll
        for (int p = 0; p < 2; p++) ldm_x4(bf[p], bAddr + p * 6400);
#pragma unroll
        for (int i = 0; i < 4; i++)
#pragma unroll
            for (int j = 0; j < 4; j++)
                mma_bf16(acc[i][j], af[i], &bf[j >> 1][(j & 1) * 2]);
        aAddr += 32;
        bAddr += 32;
    }

    __syncthreads();
    float* stage = (float*)smem;
#pragma unroll
    for (int i = 0; i < 4; i++)
#pragma unroll
        for (int j = 0; j < 4; j++) {
            int m = mw + i * 16 + (lane >> 2);
            int n = nw + j * 8 + (lane & 3) * 2;
            stage[m * 260 + n] = acc[i][j][0];
            stage[m * 260 + n + 1] = acc[i][j][1];
            stage[(m + 8) * 260 + n] = acc[i][j][2];
            stage[(m + 8) * 260 + n + 1] = acc[i][j][3];
        }
}

// ======== node GEMMs ========
__global__ void __launch_bounds__(512, 1)
gemm_node3(const __nv_bfloat16* __restrict__ A, const __nv_bfloat16* __restrict__ WpBase,
           const float* __restrict__ bnode_l,
           float* __restrict__ Cni, float* __restrict__ Cnj, float* __restrict__ Cnode) {
    extern __shared__ __align__(1024) char smem[];
    const int tid = threadIdx.x, w = tid >> 5, lane = tid & 31;
    const int row0 = blockIdx.x * 128;
    const int y = blockIdx.y;
    const __nv_bfloat16* Wp = WpBase + (size_t)y * (256 * 192);
    float* C = (y == 0) ? Cni : (y == 1) ? Cnj : Cnode;
    const float* bias = (y == 2) ? bnode_l : nullptr;

    mma_tile_to_stage(smem, A, Wp, row0, N_NODES, tid, w, lane);
    __syncthreads();

    float* stage = (float*)smem;
    int rows = min(128, N_NODES - row0);
    for (int u = tid; u < rows * 64; u += 512) {
        int m2 = u >> 6, c4 = (u & 63) * 4;
        float4 v = *(float4*)(stage + m2 * 260 + c4);
        if (bias) {
            float4 bb = *(const float4*)(bias + c4);
            v.x += bb.x; v.y += bb.y; v.z += bb.z; v.w += bb.w;
        }
        *(float4*)(C + (size_t)(row0 + m2) * 256 + c4) = v;
    }
}

// ======== fused edge GEMM + scores + next-layer f ========
__global__ void __launch_bounds__(512, 1)
gemm_edge(const __nv_bfloat16* __restrict__ A, const __nv_bfloat16* __restrict__ Wp,
          const float* __restrict__ bias_e_l, const float* __restrict__ attn_l,
          const int* __restrict__ src, const int* __restrict__ dst) {
    extern __shared__ __align__(1024) char smem[];
    const int tid = threadIdx.x, w = tid >> 5, lane = tid & 31;
    const int row0 = blockIdx.x * 128;

    mma_tile_to_stage(smem, A, Wp, row0, N_EDGES, tid, w, lane);

    int* sSrc = (int*)(smem + 133120);
    int* sDst = (int*)(smem + 133632);
    float* sAttn = (float*)(smem + 134144);
    float* sBias = (float*)(smem + 135168);
    if (tid < 128) {
        int e = row0 + tid;
        sSrc[tid] = (e < N_EDGES) ? src[e] : 0;
        sDst[tid] = (e < N_EDGES) ? dst[e] : 0;
    } else if (tid < 384) {
        sAttn[tid - 128] = attn_l[tid - 128];
    } else {
        int c = (tid - 384) * 2;
        sBias[c] = bias_e_l[c];
        sBias[c + 1] = bias_e_l[c + 1];
    }
    __syncthreads();

    float* stage = (float*)smem;
    for (int k = 0; k < 8; k++) {
        int el = w * 8 + k;
        int e = row0 + el;
        if (e >= N_EDGES) break;
        int s = sSrc[el], d = sDst[el];
        const float* pni = g_hni + (size_t)s * HC;
        const float* pnj = g_hnj + (size_t)d * HC;

        float v[8];
#pragma unroll
        for (int j = 0; j < 8; j++) {
            int c = lane + 32 * j;
            v[j] = stage[el * 260 + c] + pni[c] + pnj[c] + sBias[c];
        }
        float p[NHEAD];
#pragma unroll
        for (int h = 0; h < NHEAD; h++) {
            float a0 = sAttn[h * 64 + lane];
            float a1 = sAttn[h * 64 + lane + 32];
            float x0 = v[2 * h], x1 = v[2 * h + 1];
            float l0 = x0 > 0.f ? x0 : 0.01f * x0;
            float l1 = x1 > 0.f ? x1 : 0.01f * x1;
            p[h] = l0 * a0 + l1 * a1;
        }
#pragma unroll
        for (int o = 16; o; o >>= 1) {
#pragma unroll
            for (int h = 0; h < NHEAD; h++)
                p[h] += __shfl_xor_sync(0xffffffffu, p[h], o);
        }
        if (lane < NHEAD) g_score[e * NHEAD + lane] = p[lane];

        float m0 = 0.25f * (v[0] + v[2] + v[4] + v[6]);
        float m1 = 0.25f * (v[1] + v[3] + v[5] + v[7]);
        float sum = warp_sum(m0 + m1);
        float sq = warp_sum(m0 * m0 + m1 * m1);
        float mean = sum * (1.f / 64.f);
        float var = sq * (1.f / 64.f) - mean * mean;
        float rs = rsqrtf(var + 1e-5f);
        float f0 = eluf((m0 - mean) * rs);
        float f1 = eluf((m1 - mean) * rs);
        __nv_bfloat16 h0 = __float2bfloat16(f0);
        __nv_bfloat16 h1 = __float2bfloat16(f1);
        size_t b = (size_t)e * 128;
        g_fs[b + lane] = h0;
        g_fs[b + lane + 32] = h1;
        g_fs[b + 64 + lane] = __float2bfloat16(f0 - __bfloat162float(h0));
        g_fs[b + 96 + lane] = __float2bfloat16(f1 - __bfloat162float(h1));
    }
}

// ======== node gather: softmax + aggregate + instnorm + elu (warp per node, no atomics) ========
__global__ void __launch_bounds__(256)
node_gather(const int* __restrict__ src) {
    int n = (blockIdx.x * blockDim.x + threadIdx.x) >> 5;
    if (n >= N_NODES) return;
    int lane = threadIdx.x & 31;
    int off0 = g_off[n], off1 = g_off[n + 1];

    float h0 = 0.f, h1 = 0.f;
    if (off0 < off1) {
        // pass A: per-head max
        float mx0 = -1e30f, mx1 = -1e30f, mx2 = -1e30f, mx3 = -1e30f;
        for (int i = off0 + lane; i < off1; i += 32) {
            int e = g_eidx[i];
            float4 s = *(const float4*)(g_score + (size_t)e * 4);
            mx0 = fmaxf(mx0, s.x); mx1 = fmaxf(mx1, s.y);
            mx2 = fmaxf(mx2, s.z); mx3 = fmaxf(mx3, s.w);
        }
        mx0 = warp_max(mx0); mx1 = warp_max(mx1);
        mx2 = warp_max(mx2); mx3 = warp_max(mx3);

        // pass B: chunks of 32 edges; each lane computes w for one edge,
        // broadcast via shuffle while all lanes gather hproj channels.
        float den0 = 0.f, den1 = 0.f, den2 = 0.f, den3 = 0.f;
        float a0h[4] = {0.f, 0.f, 0.f, 0.f};   // channel lane
        float a1h[4] = {0.f, 0.f, 0.f, 0.f};   // channel lane+32
        for (int chunk = off0; chunk < off1; chunk += 32) {
            int i = chunk + lane;
            float wx = 0.f, wy = 0.f, wz = 0.f, ww = 0.f;
            int se = 0;
            if (i < off1) {
                int e = g_eidx[i];
                float4 s = *(const float4*)(g_score + (size_t)e * 4);
                wx = __expf(s.x - mx0); wy = __expf(s.y - mx1);
                wz = __expf(s.z - mx2); ww = __expf(s.w - mx3);
                se = src[e];
            }
            den0 += wx; den1 += wy; den2 += wz; den3 += ww;
            int cnt = min(32, off1 - chunk);
            for (int j = 0; j < cnt; j++) {
                float bx = __shfl_sync(0xffffffffu, wx, j);
                float by = __shfl_sync(0xffffffffu, wy, j);
                float bz = __shfl_sync(0xffffffffu, wz, j);
                float bw = __shfl_sync(0xffffffffu, ww, j);
                int sj = __shfl_sync(0xffffffffu, se, j);
                const float* hp = g_hproj + (size_t)sj * HC;
                a0h[0] += hp[lane] * bx;
                a0h[1] += hp[64 + lane] * by;
                a0h[2] += hp[128 + lane] * bz;
                a0h[3] += hp[192 + lane] * bw;
                a1h[0] += hp[32 + lane] * bx;
                a1h[1] += hp[96 + lane] * by;
                a1h[2] += hp[160 + lane] * bz;
                a1h[3] += hp[224 + lane] * bw;
            }
        }
        den0 = warp_sum(den0); den1 = warp_sum(den1);
        den2 = warp_sum(den2); den3 = warp_sum(den3);
        float r0 = 1.f / den0, r1 = 1.f / den1, r2 = 1.f / den2, r3 = 1.f / den3;
        float m0 = 0.25f * (a0h[0] * r0 + a0h[1] * r1 + a0h[2] * r2 + a0h[3] * r3);
        float m1 = 0.25f * (a1h[0] * r0 + a1h[1] * r1 + a1h[2] * r2 + a1h[3] * r3);

        float sum = warp_sum(m0 + m1);
        float sq = warp_sum(m0 * m0 + m1 * m1);
        float mean = sum * (1.f / 64.f);
        float var = sq * (1.f / 64.f) - mean * mean;
        float rs = rsqrtf(var + 1e-5f);
        h0 = eluf((m0 - mean) * rs);
        h1 = eluf((m1 - mean) * rs);
    }

    g_h[(size_t)n * CH + lane] = h0;
    g_h[(size_t)n * CH + lane + 32] = h1;
    __nv_bfloat16 b0 = __float2bfloat16(h0);
    __nv_bfloat16 b1 = __float2bfloat16(h1);
    size_t b = (size_t)n * 128;
    g_hs[b + lane] = b0;
    g_hs[b + lane + 32] = b1;
    g_hs[b + 64 + lane] = __float2bfloat16(h0 - __bfloat162float(b0));
    g_hs[b + 96 + lane] = __float2bfloat16(h1 - __bfloat162float(b1));
}

// ---------------- fp32 SGEMM ----------------
__global__ void gemm64(const float* __restrict__ A, const float* __restrict__ B,
                       const float* __restrict__ bias, float* __restrict__ Cout,
                       __nv_bfloat16* __restrict__ Csplit,
                       int M, int K, int Nt) {
    __shared__ __align__(16) float sAt[65][68];
    __shared__ __align__(16) float sB[65][68];
    const int row0 = blockIdx.x * 64;
    const int col0 = blockIdx.y * 64;
    const int tid = threadIdx.x;

    for (int idx = tid; idx < 64 * K; idx += 256) {
        int r = idx / K, k = idx - r * K;
        sAt[k][r] = (row0 + r < M) ? A[(size_t)(row0 + r) * K + k] : 0.f;
    }
    for (int idx = tid; idx < K * 64; idx += 256) {
        int k = idx >> 6, c = idx & 63;
        sB[k][c] = B[(size_t)k * Nt + col0 + c];
    }
    __syncthreads();

    const int tx = tid & 15, ty = tid >> 4;
    float acc[4][4];
#pragma unroll
    for (int i = 0; i < 4; i++)
#pragma unroll
        for (int j = 0; j < 4; j++) acc[i][j] = 0.f;

#pragma unroll 4
    for (int k = 0; k < K; k++) {
        float4 a4 = *(const float4*)&sAt[k][ty * 4];
        float4 b4 = *(const float4*)&sB[k][tx * 4];
        float aa[4] = {a4.x, a4.y, a4.z, a4.w};
        float bb[4] = {b4.x, b4.y, b4.z, b4.w};
#pragma unroll
        for (int i = 0; i < 4; i++)
#pragma unroll
            for (int j = 0; j < 4; j++) acc[i][j] += aa[i] * bb[j];
    }
    float bv[4];
#pragma unroll
    for (int j = 0; j < 4; j++) bv[j] = bias ? bias[col0 + tx * 4 + j] : 0.f;
#pragma unroll
    for (int i = 0; i < 4; i++) {
        int r = row0 + ty * 4 + i;
        if (r < M) {
#pragma unroll
            for (int j = 0; j < 4; j++) {
                float val = acc[i][j] + bv[j];
                int col = col0 + tx * 4 + j;
                if (Cout) Cout[(size_t)r * Nt + col] = val;
                if (Csplit) {
                    __nv_bfloat16 hi = __float2bfloat16(val);
                    Csplit[(size_t)r * 128 + col] = hi;
                    Csplit[(size_t)r * 128 + 64 + col] = __float2bfloat16(val - __bfloat162float(hi));
                }
            }
        }
    }
}

// ---------------- weight prep ----------------
__global__ void prep_all(const float* __restrict__ Wni, const float* __restrict__ Wnj,
                         const float* __restrict__ Wnode, const float* __restrict__ Wfij) {
    int mat = blockIdx.x / 192;
    int idx = (blockIdx.x % 192) * 256 + threadIdx.x;
    int l = mat >> 2, type = mat & 3;
    const float* W = (type == 0 ? Wni : type == 1 ? Wnj : type == 2 ? Wnode : Wfij)
                     + (size_t)l * 64 * 256;
    __nv_bfloat16* Wp = g_wprep + (size_t)mat * (256 * 192);
    int n = idx / 192, kk = idx - n * 192;
    int k = kk & 63;
    float v = W[(size_t)k * 256 + n];
    __nv_bfloat16 hi = __float2bfloat16(v);
    __nv_bfloat16 out = hi;
    if (kk >= 64 && kk < 128) out = __float2bfloat16(v - __bfloat162float(hi));
    Wp[idx] = out;
}

// ---------------- CSR build ----------------
__global__ void csr_zero() {
    int i = blockIdx.x * blockDim.x + threadIdx.x;
    if (i < N_NODES) g_deg[i] = 0;
}
__global__ void csr_hist(const int* __restrict__ dst) {
    int e = blockIdx.x * blockDim.x + threadIdx.x;
    if (e < N_EDGES) atomicAdd(&g_deg[dst[e]], 1);
}
__global__ void __launch_bounds__(1024) csr_scan() {
    __shared__ int ssum[1024];
    int t = threadIdx.x;
    int base = t * 20;
    int s = 0;
    int loc[20];
#pragma unroll
    for (int j = 0; j < 20; j++) {
        int idx = base + j;
        loc[j] = s;
        if (idx < N_NODES) s += g_deg[idx];
    }
    ssum[t] = s;
    __syncthreads();
    for (int o = 1; o < 1024; o <<= 1) {
        int v = (t >= o) ? ssum[t - o] : 0;
        __syncthreads();
        ssum[t] += v;
        __syncthreads();
    }
    int pre = (t == 0) ? 0 : ssum[t - 1];
#pragma unroll
    for (int j = 0; j < 20; j++) {
        int idx = base + j;
        if (idx < N_NODES) {
            int o = pre + loc[j];
            g_off[idx] = o;
            g_cursor[idx] = o;
        }
    }
    if (t == 1023) g_off[N_NODES] = ssum[1023];
}
__global__ void csr_scatter(const int* __restrict__ dst) {
    int e = blockIdx.x * blockDim.x + threadIdx.x;
    if (e >= N_EDGES) return;
    int pos = atomicAdd(&g_cursor[dst[e]], 1);
    g_eidx[pos] = e;
}

// ---------------- launcher ----------------
extern "C" void kernel_launch(void* const* d_in, const int* in_sizes, int n_in,
                              void* d_out, int out_size) {
    const float* x = (const float*)d_in[0];
    const float* efeat = (const float*)d_in[1];
    const int* src = (const int*)d_in[2];
    const int* dst = (const int*)d_in[3];
    const float* Wn0 = (const float*)d_in[4];
    const float* bn0 = (const float*)d_in[5];
    const float* We0 = (const float*)d_in[6];
    const float* be0 = (const float*)d_in[7];
    const float* Wnode = (const float*)d_in[8];
    const float* bnode = (const float*)d_in[9];
    const float* Wni = (const float*)d_in[10];
    const float* Wnj = (const float*)d_in[11];
    const float* Wfij = (const float*)d_in[12];
    const float* attn = (const float*)d_in[13];
    const float* bias_e = (const float*)d_in[14];
    const float* Wf = (const float*)d_in[15];
    const float* bf = (const float*)d_in[16];

    float *ph, *phni, *phnj, *phproj;
    __nv_bfloat16 *phs, *pfs, *pwp;
    cudaGetSymbolAddress((void**)&ph, g_h);
    cudaGetSymbolAddress((void**)&phni, g_hni);
    cudaGetSymbolAddress((void**)&phnj, g_hnj);
    cudaGetSymbolAddress((void**)&phproj, g_hproj);
    cudaGetSymbolAddress((void**)&phs, g_hs);
    cudaGetSymbolAddress((void**)&pfs, g_fs);
    cudaGetSymbolAddress((void**)&pwp, g_wprep);

    cudaFuncSetAttribute(gemm_node3, cudaFuncAttributeMaxDynamicSharedMemorySize, MM_SMEM);
    cudaFuncSetAttribute(gemm_edge, cudaFuncAttributeMaxDynamicSharedMemorySize, MM_SMEM);

    const dim3 blk(256);
    const int NB_N = (N_NODES + 63) / 64;
    const int NB_E = (N_EDGES + 63) / 64;
    const int TB_N = (N_NODES + 127) / 128;   // 157
    const int TB_E = (N_EDGES + 127) / 128;   // 1563
    const int WPSZ = 256 * 192;

    // CSR build (dst is layer-invariant)
    csr_zero<<<(N_NODES + 255) / 256, blk>>>();
    csr_hist<<<(N_EDGES + 255) / 256, blk>>>(dst);
    csr_scan<<<1, 1024>>>();
    csr_scatter<<<(N_EDGES + 255) / 256, blk>>>(dst);

    prep_all<<<8 * 192, blk>>>(Wni, Wnj, Wnode, Wfij);
    gemm64<<<dim3(NB_N, 1), blk>>>(x, Wn0, bn0, nullptr, phs, N_NODES, 65, 64);
    gemm64<<<dim3(NB_E, 1), blk>>>(efeat, We0, be0, nullptr, pfs, N_EDGES, 15, 64);

    for (int l = 0; l < 2; l++) {
        const float* bnode_l = bnode + (size_t)l * 256;
        const float* bias_e_l = bias_e + (size_t)l * 256;
        const float* attn_l = attn + (size_t)l * 256;

        gemm_node3<<<dim3(TB_N, 3), 512, MM_SMEM>>>(phs, pwp + (size_t)(l * 4) * WPSZ,
                                                    bnode_l, phni, phnj, phproj);
        gemm_edge<<<TB_E, 512, MM_SMEM>>>(pfs, pwp + (size_t)(l * 4 + 3) * WPSZ,
                                          bias_e_l, attn_l, src, dst);
        node_gather<<<(N_NODES * 32 + 255) / 256, blk>>>(src);
    }

    gemm64<<<dim3(NB_N, 1), blk>>>(ph, Wf, bf, (float*)d_out, nullptr, N_NODES, 64, 64);
}

// round 7
// speedup vs baseline: 1.6405x; 1.0335x over previous
#include <cuda_runtime.h>
#include <cuda_bf16.h>
#include <math.h>
#include <stdint.h>

#define N_NODES 20000
#define N_EDGES 200000
#define CH 64
#define HC 256
#define NHEAD 4

// ---------------- scratch ----------------
__device__ __align__(256) float    g_h[N_NODES * CH];
__device__ __align__(256) __nv_bfloat16 g_hs[N_NODES * 128];
__device__ __align__(256) __nv_bfloat16 g_fs[N_EDGES * 128];
__device__ __align__(256) __nv_bfloat16 g_es[N_EDGES * 48];     // efeat split (K'=48)
__device__ __align__(256) __nv_bfloat16 g_wprep[8 * 256 * 192];
__device__ __align__(256) __nv_bfloat16 g_wce0[256 * 48];       // combined We0@Wfij0, split
__device__ __align__(256) float    g_bce0[256];                 // combined bias
__device__ __align__(256) float    g_hni[N_NODES * HC];
__device__ __align__(256) float    g_hnj[N_NODES * HC];
__device__ __align__(256) float    g_hproj[N_NODES * HC];
__device__ __align__(256) float    g_score[N_EDGES * NHEAD];
// CSR by dst
__device__ __align__(256) int g_deg[N_NODES];
__device__ __align__(256) int g_off[N_NODES + 1];
__device__ __align__(256) int g_cursor[N_NODES];
__device__ __align__(256) int g_eidx[N_EDGES];

// ---------------- helpers ----------------
__device__ __forceinline__ uint32_t smem_u32(const void* p) {
    uint32_t a;
    asm("{ .reg .u64 t; cvta.to.shared.u64 t, %1; cvt.u32.u64 %0, t; }" : "=r"(a) : "l"(p));
    return a;
}
__device__ __forceinline__ float eluf(float x) { return x > 0.f ? x : expm1f(x); }
__device__ __forceinline__ float warp_sum(float v) {
#pragma unroll
    for (int o = 16; o; o >>= 1) v += __shfl_xor_sync(0xffffffffu, v, o);
    return v;
}
__device__ __forceinline__ float warp_max(float v) {
#pragma unroll
    for (int o = 16; o; o >>= 1) v = fmaxf(v, __shfl_xor_sync(0xffffffffu, v, o));
    return v;
}
__device__ __forceinline__ void ldm_x4(uint32_t* r, uint32_t addr) {
    asm volatile("ldmatrix.sync.aligned.m8n8.x4.shared.b16 {%0,%1,%2,%3}, [%4];"
                 : "=r"(r[0]), "=r"(r[1]), "=r"(r[2]), "=r"(r[3]) : "r"(addr));
}
__device__ __forceinline__ void mma_bf16(float* d, const uint32_t* a, const uint32_t* b) {
    asm volatile("mma.sync.aligned.m16n8k16.row.col.f32.bf16.bf16.f32 "
                 "{%0,%1,%2,%3}, {%4,%5,%6,%7}, {%8,%9}, {%0,%1,%2,%3};"
                 : "+f"(d[0]), "+f"(d[1]), "+f"(d[2]), "+f"(d[3])
                 : "r"(a[0]), "r"(a[1]), "r"(a[2]), "r"(a[3]), "r"(b[0]), "r"(b[1]));
}

#define MM_SMEM 153600

// ======== core mma tile (templated K): fill, mma, stage to smem [128][260] ========
template<int KSTEPS, bool REMAP>
__device__ __forceinline__ void mma_tile_to_stage(
    char* smem, const __nv_bfloat16* __restrict__ A, const __nv_bfloat16* __restrict__ Wp,
    int row0, int M, int tid, int w, int lane) {
    constexpr int KELEM = KSTEPS * 16;
    constexpr int STRIDE = KELEM + 8;
    constexpr int AROW = REMAP ? 128 : KELEM;
    constexpr int CPR = KELEM / 8;
    constexpr int TILEB = 16 * STRIDE * 2;
    __nv_bfloat16* smA = (__nv_bfloat16*)smem;
    __nv_bfloat16* smB = (__nv_bfloat16*)(smem + 128 * STRIDE * 2);

    for (int u = tid; u < 128 * CPR; u += 512) {
        int m = u / CPR, k0 = (u % CPR) * 8;
        int sc = REMAP ? ((k0 & 63) + (k0 >= 128 ? 64 : 0)) : k0;
        int mm = row0 + m < M ? row0 + m : M - 1;
        int bytes = (row0 + m < M) ? 16 : 0;
        const void* gp = A + (size_t)mm * AROW + sc;
        uint32_t sa = smem_u32(smA + m * STRIDE + k0);
        asm volatile("cp.async.cg.shared.global [%0], [%1], 16, %2;"
                     :: "r"(sa), "l"(gp), "r"(bytes));
    }
    for (int u = tid; u < 256 * CPR; u += 512) {
        int n = u / CPR, k0 = (u % CPR) * 8;
        uint32_t sa = smem_u32(smB + n * STRIDE + k0);
        asm volatile("cp.async.cg.shared.global [%0], [%1], 16;"
                     :: "r"(sa), "l"(Wp + (size_t)n * KELEM + k0));
    }
    asm volatile("cp.async.commit_group;");
    asm volatile("cp.async.wait_group 0;" ::: "memory");
    __syncthreads();

    const int mw = (w >> 3) * 64;
    const int nw = (w & 7) * 32;
    const int g = lane >> 3, r = lane & 7;

    float acc[4][4][4];
#pragma unroll
    for (int i = 0; i < 4; i++)
#pragma unroll
        for (int j = 0; j < 4; j++)
#pragma unroll
            for (int q = 0; q < 4; q++) acc[i][j][q] = 0.f;

    uint32_t aAddr = smem_u32(smA) + ((mw + (g & 1) * 8 + r) * STRIDE + (g >> 1) * 8) * 2;
    uint32_t bAddr = smem_u32(smB) + ((nw + (g >> 1) * 8 + r) * STRIDE + (g & 1) * 8) * 2;

#pragma unroll
    for (int ks = 0; ks < KSTEPS; ks++) {
        uint32_t af[4][4], bf[2][4];
#pragma unroll
        for (int i = 0; i < 4; i++) ldm_x4(af[i], aAddr + i * TILEB);
#pragma unroll
        for (int p = 0; p < 2; p++) ldm_x4(bf[p], bAddr + p * TILEB);
#pragma unroll
        for (int i = 0; i < 4; i++)
#pragma unroll
            for (int j = 0; j < 4; j++)
                mma_bf16(acc[i][j], af[i], &bf[j >> 1][(j & 1) * 2]);
        aAddr += 32;
        bAddr += 32;
    }

    __syncthreads();
    float* stage = (float*)smem;
#pragma unroll
    for (int i = 0; i < 4; i++)
#pragma unroll
        for (int j = 0; j < 4; j++) {
            int m = mw + i * 16 + (lane >> 2);
            int n = nw + j * 8 + (lane & 3) * 2;
            stage[m * 260 + n] = acc[i][j][0];
            stage[m * 260 + n + 1] = acc[i][j][1];
            stage[(m + 8) * 260 + n] = acc[i][j][2];
            stage[(m + 8) * 260 + n + 1] = acc[i][j][3];
        }
}

// ======== node GEMMs ========
__global__ void __launch_bounds__(512, 1)
gemm_node3(const __nv_bfloat16* __restrict__ A, const __nv_bfloat16* __restrict__ WpBase,
           const float* __restrict__ bnode_l,
           float* __restrict__ Cni, float* __restrict__ Cnj, float* __restrict__ Cnode) {
    extern __shared__ __align__(1024) char smem[];
    const int tid = threadIdx.x, w = tid >> 5, lane = tid & 31;
    const int row0 = blockIdx.x * 128;
    const int y = blockIdx.y;
    const __nv_bfloat16* Wp = WpBase + (size_t)y * (256 * 192);
    float* C = (y == 0) ? Cni : (y == 1) ? Cnj : Cnode;
    const float* bias = (y == 2) ? bnode_l : nullptr;

    mma_tile_to_stage<12, true>(smem, A, Wp, row0, N_NODES, tid, w, lane);
    __syncthreads();

    float* stage = (float*)smem;
    int rows = min(128, N_NODES - row0);
    for (int u = tid; u < rows * 64; u += 512) {
        int m2 = u >> 6, c4 = (u & 63) * 4;
        float4 v = *(float4*)(stage + m2 * 260 + c4);
        if (bias) {
            float4 bb = *(const float4*)(bias + c4);
            v.x += bb.x; v.y += bb.y; v.z += bb.z; v.w += bb.w;
        }
        *(float4*)(C + (size_t)(row0 + m2) * 256 + c4) = v;
    }
}

// per-edge epilogue body (warp-collective)
__device__ __forceinline__ void edge_finish(int e, int d, float* v, const float* sAttn, int lane) {
    float p[NHEAD];
#pragma unroll
    for (int h = 0; h < NHEAD; h++) {
        float a0 = sAttn[h * 64 + lane];
        float a1 = sAttn[h * 64 + lane + 32];
        float x0 = v[2 * h], x1 = v[2 * h + 1];
        float l0 = x0 > 0.f ? x0 : 0.01f * x0;
        float l1 = x1 > 0.f ? x1 : 0.01f * x1;
        p[h] = l0 * a0 + l1 * a1;
    }
#pragma unroll
    for (int o = 16; o; o >>= 1) {
#pragma unroll
        for (int h = 0; h < NHEAD; h++)
            p[h] += __shfl_xor_sync(0xffffffffu, p[h], o);
    }
    if (lane < NHEAD) g_score[e * NHEAD + lane] = p[lane];

    float m0 = 0.25f * (v[0] + v[2] + v[4] + v[6]);
    float m1 = 0.25f * (v[1] + v[3] + v[5] + v[7]);
    float sum = warp_sum(m0 + m1);
    float sq = warp_sum(m0 * m0 + m1 * m1);
    float mean = sum * (1.f / 64.f);
    float var = sq * (1.f / 64.f) - mean * mean;
    float rs = rsqrtf(var + 1e-5f);
    float f0 = eluf((m0 - mean) * rs);
    float f1 = eluf((m1 - mean) * rs);
    __nv_bfloat16 h0 = __float2bfloat16(f0);
    __nv_bfloat16 h1 = __float2bfloat16(f1);
    size_t b = (size_t)e * 128;
    g_fs[b + lane] = h0;
    g_fs[b + lane + 32] = h1;
    g_fs[b + 64 + lane] = __float2bfloat16(f0 - __bfloat162float(h0));
    g_fs[b + 96 + lane] = __float2bfloat16(f1 - __bfloat162float(h1));
}

// ======== fused edge GEMM + scores + next-layer f (templated K) ========
template<int KSTEPS, bool REMAP>
__global__ void __launch_bounds__(512, 1)
gemm_edge(const __nv_bfloat16* __restrict__ A, const __nv_bfloat16* __restrict__ Wp,
          const float* __restrict__ bias_e_l, const float* __restrict__ attn_l,
          const int* __restrict__ src, const int* __restrict__ dst) {
    extern __shared__ __align__(1024) char smem[];
    const int tid = threadIdx.x, w = tid >> 5, lane = tid & 31;
    const int row0 = blockIdx.x * 128;

    mma_tile_to_stage<KSTEPS, REMAP>(smem, A, Wp, row0, N_EDGES, tid, w, lane);

    int* sSrc = (int*)(smem + 133120);
    int* sDst = (int*)(smem + 133632);
    float* sAttn = (float*)(smem + 134144);
    float* sBias = (float*)(smem + 135168);
    if (tid < 128) {
        int e = row0 + tid;
        sSrc[tid] = (e < N_EDGES) ? src[e] : 0;
        sDst[tid] = (e < N_EDGES) ? dst[e] : 0;
    } else if (tid < 384) {
        sAttn[tid - 128] = attn_l[tid - 128];
    } else {
        int c = (tid - 384) * 2;
        sBias[c] = bias_e_l[c];
        sBias[c + 1] = bias_e_l[c + 1];
    }
    __syncthreads();

    float* stage = (float*)smem;
    // 2-edge interleave for memory-level parallelism
    for (int k = 0; k < 8; k += 2) {
        int el0 = w * 8 + k;
        int e0 = row0 + el0, e1 = e0 + 1;
        if (e0 >= N_EDGES) break;
        bool ok1 = (e1 < N_EDGES);
        int s0 = sSrc[el0], d0 = sDst[el0];
        int s1 = sSrc[el0 + 1], d1 = sDst[el0 + 1];
        const float* pni0 = g_hni + (size_t)s0 * HC;
        const float* pnj0 = g_hnj + (size_t)d0 * HC;
        const float* pni1 = g_hni + (size_t)s1 * HC;
        const float* pnj1 = g_hnj + (size_t)d1 * HC;

        float v0[8], v1[8];
#pragma unroll
        for (int j = 0; j < 8; j++) {
            int c = lane + 32 * j;
            v0[j] = stage[el0 * 260 + c] + pni0[c] + pnj0[c] + sBias[c];
            v1[j] = stage[(el0 + 1) * 260 + c] + pni1[c] + pnj1[c] + sBias[c];
        }
        edge_finish(e0, d0, v0, sAttn, lane);
        if (ok1) edge_finish(e1, d1, v1, sAttn, lane);
    }
}

// ======== node gather: softmax + aggregate + instnorm + elu ========
__global__ void __launch_bounds__(256)
node_gather(const int* __restrict__ src) {
    int n = (blockIdx.x * blockDim.x + threadIdx.x) >> 5;
    if (n >= N_NODES) return;
    int lane = threadIdx.x & 31;
    int off0 = g_off[n], off1 = g_off[n + 1];

    float h0 = 0.f, h1 = 0.f;
    if (off0 < off1) {
        float mx0 = -1e30f, mx1 = -1e30f, mx2 = -1e30f, mx3 = -1e30f;
        for (int i = off0 + lane; i < off1; i += 32) {
            int e = g_eidx[i];
            float4 s = *(const float4*)(g_score + (size_t)e * 4);
            mx0 = fmaxf(mx0, s.x); mx1 = fmaxf(mx1, s.y);
            mx2 = fmaxf(mx2, s.z); mx3 = fmaxf(mx3, s.w);
        }
        mx0 = warp_max(mx0); mx1 = warp_max(mx1);
        mx2 = warp_max(mx2); mx3 = warp_max(mx3);

        float den0 = 0.f, den1 = 0.f, den2 = 0.f, den3 = 0.f;
        float a0h[4] = {0.f, 0.f, 0.f, 0.f};
        float a1h[4] = {0.f, 0.f, 0.f, 0.f};
        for (int chunk = off0; chunk < off1; chunk += 32) {
            int i = chunk + lane;
            float wx = 0.f, wy = 0.f, wz = 0.f, ww = 0.f;
            int se = 0;
            if (i < off1) {
                int e = g_eidx[i];
                float4 s = *(const float4*)(g_score + (size_t)e * 4);
                wx = __expf(s.x - mx0); wy = __expf(s.y - mx1);
                wz = __expf(s.z - mx2); ww = __expf(s.w - mx3);
                se = src[e];
            }
            den0 += wx; den1 += wy; den2 += wz; den3 += ww;
            int cnt = min(32, off1 - chunk);
            int j = 0;
            for (; j + 1 < cnt; j += 2) {
                float bx0 = __shfl_sync(0xffffffffu, wx, j);
                float by0 = __shfl_sync(0xffffffffu, wy, j);
                float bz0 = __shfl_sync(0xffffffffu, wz, j);
                float bw0 = __shfl_sync(0xffffffffu, ww, j);
                int sj0 = __shfl_sync(0xffffffffu, se, j);
                float bx1 = __shfl_sync(0xffffffffu, wx, j + 1);
                float by1 = __shfl_sync(0xffffffffu, wy, j + 1);
                float bz1 = __shfl_sync(0xffffffffu, wz, j + 1);
                float bw1 = __shfl_sync(0xffffffffu, ww, j + 1);
                int sj1 = __shfl_sync(0xffffffffu, se, j + 1);
                const float* hp0 = g_hproj + (size_t)sj0 * HC;
                const float* hp1 = g_hproj + (size_t)sj1 * HC;
                float t00 = hp0[lane],       t10 = hp1[lane];
                float t01 = hp0[64 + lane],  t11 = hp1[64 + lane];
                float t02 = hp0[128 + lane], t12 = hp1[128 + lane];
                float t03 = hp0[192 + lane], t13 = hp1[192 + lane];
                float u00 = hp0[32 + lane],  u10 = hp1[32 + lane];
                float u01 = hp0[96 + lane],  u11 = hp1[96 + lane];
                float u02 = hp0[160 + lane], u12 = hp1[160 + lane];
                float u03 = hp0[224 + lane], u13 = hp1[224 + lane];
                a0h[0] += t00 * bx0 + t10 * bx1;
                a0h[1] += t01 * by0 + t11 * by1;
                a0h[2] += t02 * bz0 + t12 * bz1;
                a0h[3] += t03 * bw0 + t13 * bw1;
                a1h[0] += u00 * bx0 + u10 * bx1;
                a1h[1] += u01 * by0 + u11 * by1;
                a1h[2] += u02 * bz0 + u12 * bz1;
                a1h[3] += u03 * bw0 + u13 * bw1;
            }
            if (j < cnt) {
                float bx = __shfl_sync(0xffffffffu, wx, j);
                float by = __shfl_sync(0xffffffffu, wy, j);
                float bz = __shfl_sync(0xffffffffu, wz, j);
                float bw = __shfl_sync(0xffffffffu, ww, j);
                int sj = __shfl_sync(0xffffffffu, se, j);
                const float* hp = g_hproj + (size_t)sj * HC;
                a0h[0] += hp[lane] * bx;
                a0h[1] += hp[64 + lane] * by;
                a0h[2] += hp[128 + lane] * bz;
                a0h[3] += hp[192 + lane] * bw;
                a1h[0] += hp[32 + lane] * bx;
                a1h[1] += hp[96 + lane] * by;
                a1h[2] += hp[160 + lane] * bz;
                a1h[3] += hp[224 + lane] * bw;
            }
        }
        den0 = warp_sum(den0); den1 = warp_sum(den1);
        den2 = warp_sum(den2); den3 = warp_sum(den3);
        float r0 = 1.f / den0, r1 = 1.f / den1, r2 = 1.f / den2, r3 = 1.f / den3;
        float m0 = 0.25f * (a0h[0] * r0 + a0h[1] * r1 + a0h[2] * r2 + a0h[3] * r3);
        float m1 = 0.25f * (a1h[0] * r0 + a1h[1] * r1 + a1h[2] * r2 + a1h[3] * r3);

        float sum = warp_sum(m0 + m1);
        float sq = warp_sum(m0 * m0 + m1 * m1);
        float mean = sum * (1.f / 64.f);
        float var = sq * (1.f / 64.f) - mean * mean;
        float rs = rsqrtf(var + 1e-5f);
        h0 = eluf((m0 - mean) * rs);
        h1 = eluf((m1 - mean) * rs);
    }

    g_h[(size_t)n * CH + lane] = h0;
    g_h[(size_t)n * CH + lane + 32] = h1;
    __nv_bfloat16 b0 = __float2bfloat16(h0);
    __nv_bfloat16 b1 = __float2bfloat16(h1);
    size_t b = (size_t)n * 128;
    g_hs[b + lane] = b0;
    g_hs[b + lane + 32] = b1;
    g_hs[b + 64 + lane] = __float2bfloat16(h0 - __bfloat162float(b0));
    g_hs[b + 96 + lane] = __float2bfloat16(h1 - __bfloat162float(b1));
}

// ---------------- fp32 SGEMM (node input / final output) ----------------
__global__ void gemm64(const float* __restrict__ A, const float* __restrict__ B,
                       const float* __restrict__ bias, float* __restrict__ Cout,
                       __nv_bfloat16* __restrict__ Csplit,
                       int M, int K, int Nt) {
    __shared__ __align__(16) float sAt[65][68];
    __shared__ __align__(16) float sB[65][68];
    const int row0 = blockIdx.x * 64;
    const int col0 = blockIdx.y * 64;
    const int tid = threadIdx.x;

    for (int idx = tid; idx < 64 * K; idx += 256) {
        int r = idx / K, k = idx - r * K;
        sAt[k][r] = (row0 + r < M) ? A[(size_t)(row0 + r) * K + k] : 0.f;
    }
    for (int idx = tid; idx < K * 64; idx += 256) {
        int k = idx >> 6, c = idx & 63;
        sB[k][c] = B[(size_t)k * Nt + col0 + c];
    }
    __syncthreads();

    const int tx = tid & 15, ty = tid >> 4;
    float acc[4][4];
#pragma unroll
    for (int i = 0; i < 4; i++)
#pragma unroll
        for (int j = 0; j < 4; j++) acc[i][j] = 0.f;

#pragma unroll 4
    for (int k = 0; k < K; k++) {
        float4 a4 = *(const float4*)&sAt[k][ty * 4];
        float4 b4 = *(const float4*)&sB[k][tx * 4];
        float aa[4] = {a4.x, a4.y, a4.z, a4.w};
        float bb[4] = {b4.x, b4.y, b4.z, b4.w};
#pragma unroll
        for (int i = 0; i < 4; i++)
#pragma unroll
            for (int j = 0; j < 4; j++) acc[i][j] += aa[i] * bb[j];
    }
    float bv[4];
#pragma unroll
    for (int j = 0; j < 4; j++) bv[j] = bias ? bias[col0 + tx * 4 + j] : 0.f;
#pragma unroll
    for (int i = 0; i < 4; i++) {
        int r = row0 + ty * 4 + i;
        if (r < M) {
#pragma unroll
            for (int j = 0; j < 4; j++) {
                float val = acc[i][j] + bv[j];
                int col = col0 + tx * 4 + j;
                if (Cout) Cout[(size_t)r * Nt + col] = val;
                if (Csplit) {
                    __nv_bfloat16 hi = __float2bfloat16(val);
                    Csplit[(size_t)r * 128 + col] = hi;
                    Csplit[(size_t)r * 128 + 64 + col] = __float2bfloat16(val - __bfloat162float(hi));
                }
            }
        }
    }
}

// ---------------- weight prep ----------------
__global__ void prep_all(const float* __restrict__ Wni, const float* __restrict__ Wnj,
                         const float* __restrict__ Wnode, const float* __restrict__ Wfij) {
    int mat = blockIdx.x / 192;
    int idx = (blockIdx.x % 192) * 256 + threadIdx.x;
    int l = mat >> 2, type = mat & 3;
    const float* W = (type == 0 ? Wni : type == 1 ? Wnj : type == 2 ? Wnode : Wfij)
                     + (size_t)l * 64 * 256;
    __nv_bfloat16* Wp = g_wprep + (size_t)mat * (256 * 192);
    int n = idx / 192, kk = idx - n * 192;
    int k = kk & 63;
    float v = W[(size_t)k * 256 + n];
    __nv_bfloat16 hi = __float2bfloat16(v);
    __nv_bfloat16 out = hi;
    if (kk >= 64 && kk < 128) out = __float2bfloat16(v - __bfloat162float(hi));
    Wp[idx] = out;
}

// combined layer-0 edge weight: Wc = We0 @ Wfij0 [15,256]; bce = be0@Wfij0 + bias_e0
__global__ void prep_edge0(const float* __restrict__ We0, const float* __restrict__ be0,
                           const float* __restrict__ Wfij0, const float* __restrict__ bias_e0) {
    int n = threadIdx.x;
    float col[64];
#pragma unroll
    for (int j = 0; j < 64; j++) col[j] = Wfij0[j * 256 + n];
    float bs = bias_e0[n];
#pragma unroll
    for (int j = 0; j < 64; j++) bs += be0[j] * col[j];
    g_bce0[n] = bs;
    for (int k = 0; k < 15; k++) {
        float s = 0.f;
#pragma unroll
        for (int j = 0; j < 64; j++) s += We0[k * 64 + j] * col[j];
        __nv_bfloat16 hi = __float2bfloat16(s);
        __nv_bfloat16 lo = __float2bfloat16(s - __bfloat162float(hi));
        g_wce0[n * 48 + k] = hi;            // block0: hi
        g_wce0[n * 48 + 15 + k] = lo;       // block1: lo
        g_wce0[n * 48 + 30 + k] = hi;       // block2: hi
    }
    for (int c = 45; c < 48; c++) g_wce0[n * 48 + c] = __float2bfloat16(0.f);
}

// efeat -> split K'=48 layout [hi(15)|hi(15)|lo(15)|0(3)]
__global__ void split_efeat(const float* __restrict__ efeat) {
    int idx = blockIdx.x * blockDim.x + threadIdx.x;
    if (idx >= N_EDGES * 48) return;
    int e = idx / 48, c = idx - e * 48;
    __nv_bfloat16 out = __float2bfloat16(0.f);
    if (c < 45) {
        int k = c < 15 ? c : (c < 30 ? c - 15 : c - 30);
        float v = efeat[e * 15 + k];
        __nv_bfloat16 hi = __float2bfloat16(v);
        out = (c < 30) ? hi : __float2bfloat16(v - __bfloat162float(hi));
    }
    g_es[idx] = out;
}

// ---------------- CSR build ----------------
__global__ void csr_zero() {
    int i = blockIdx.x * blockDim.x + threadIdx.x;
    if (i < N_NODES) g_deg[i] = 0;
}
__global__ void csr_hist(const int* __restrict__ dst) {
    int e = blockIdx.x * blockDim.x + threadIdx.x;
    if (e < N_EDGES) atomicAdd(&g_deg[dst[e]], 1);
}
__global__ void __launch_bounds__(1024) csr_scan() {
    __shared__ int ssum[1024];
    int t = threadIdx.x;
    int base = t * 20;
    int s = 0;
    int loc[20];
#pragma unroll
    for (int j = 0; j < 20; j++) {
        int idx = base + j;
        loc[j] = s;
        if (idx < N_NODES) s += g_deg[idx];
    }
    ssum[t] = s;
    __syncthreads();
    for (int o = 1; o < 1024; o <<= 1) {
        int v = (t >= o) ? ssum[t - o] : 0;
        __syncthreads();
        ssum[t] += v;
        __syncthreads();
    }
    int pre = (t == 0) ? 0 : ssum[t - 1];
#pragma unroll
    for (int j = 0; j < 20; j++) {
        int idx = base + j;
        if (idx < N_NODES) {
            int o = pre + loc[j];
            g_off[idx] = o;
            g_cursor[idx] = o;
        }
    }
    if (t == 1023) g_off[N_NODES] = ssum[1023];
}
__global__ void csr_scatter(const int* __restrict__ dst) {
    int e = blockIdx.x * blockDim.x + threadIdx.x;
    if (e >= N_EDGES) return;
    int pos = atomicAdd(&g_cursor[dst[e]], 1);
    g_eidx[pos] = e;
}

// ---------------- launcher ----------------
extern "C" void kernel_launch(void* const* d_in, const int* in_sizes, int n_in,
                              void* d_out, int out_size) {
    const float* x = (const float*)d_in[0];
    const float* efeat = (const float*)d_in[1];
    const int* src = (const int*)d_in[2];
    const int* dst = (const int*)d_in[3];
    const float* Wn0 = (const float*)d_in[4];
    const float* bn0 = (const float*)d_in[5];
    const float* We0 = (const float*)d_in[6];
    const float* be0 = (const float*)d_in[7];
    const float* Wnode = (const float*)d_in[8];
    const float* bnode = (const float*)d_in[9];
    const float* Wni = (const float*)d_in[10];
    const float* Wnj = (const float*)d_in[11];
    const float* Wfij = (const float*)d_in[12];
    const float* attn = (const float*)d_in[13];
    const float* bias_e = (const float*)d_in[14];
    const float* Wf = (const float*)d_in[15];
    const float* bf = (const float*)d_in[16];

    float *ph, *phni, *phnj, *phproj, *pbce0;
    __nv_bfloat16 *phs, *pfs, *pwp, *pes, *pwce0;
    cudaGetSymbolAddress((void**)&ph, g_h);
    cudaGetSymbolAddress((void**)&phni, g_hni);
    cudaGetSymbolAddress((void**)&phnj, g_hnj);
    cudaGetSymbolAddress((void**)&phproj, g_hproj);
    cudaGetSymbolAddress((void**)&phs, g_hs);
    cudaGetSymbolAddress((void**)&pfs, g_fs);
    cudaGetSymbolAddress((void**)&pwp, g_wprep);
    cudaGetSymbolAddress((void**)&pes, g_es);
    cudaGetSymbolAddress((void**)&pwce0, g_wce0);
    cudaGetSymbolAddress((void**)&pbce0, g_bce0);

    cudaFuncSetAttribute(gemm_node3, cudaFuncAttributeMaxDynamicSharedMemorySize, MM_SMEM);
    cudaFuncSetAttribute(gemm_edge<3, false>, cudaFuncAttributeMaxDynamicSharedMemorySize, MM_SMEM);
    cudaFuncSetAttribute(gemm_edge<12, true>, cudaFuncAttributeMaxDynamicSharedMemorySize, MM_SMEM);

    const dim3 blk(256);
    const int NB_N = (N_NODES + 63) / 64;
    const int TB_N = (N_NODES + 127) / 128;   // 157
    const int TB_E = (N_EDGES + 127) / 128;   // 1563
    const int WPSZ = 256 * 192;

    // CSR build (dst is layer-invariant)
    csr_zero<<<(N_NODES + 255) / 256, blk>>>();
    csr_hist<<<(N_EDGES + 255) / 256, blk>>>(dst);
    csr_scan<<<1, 1024>>>();
    csr_scatter<<<(N_EDGES + 255) / 256, blk>>>(dst);

    // preps
    prep_all<<<8 * 192, blk>>>(Wni, Wnj, Wnode, Wfij);
    prep_edge0<<<1, 256>>>(We0, be0, Wfij, bias_e);
    split_efeat<<<(N_EDGES * 48 + 255) / 256, blk>>>(efeat);

    // node input projection (fp32 -> split bf16)
    gemm64<<<dim3(NB_N, 1), blk>>>(x, Wn0, bn0, nullptr, phs, N_NODES, 65, 64);

    // ---- layer 0 ----
    gemm_node3<<<dim3(TB_N, 3), 512, MM_SMEM>>>(phs, pwp, bnode, phni, phnj, phproj);
    gemm_edge<3, false><<<TB_E, 512, MM_SMEM>>>(pes, pwce0, pbce0, attn, src, dst);
    node_gather<<<(N_NODES * 32 + 255) / 256, blk>>>(src);

    // ---- layer 1 ----
    gemm_node3<<<dim3(TB_N, 3), 512, MM_SMEM>>>(phs, pwp + (size_t)4 * WPSZ,
                                                bnode + 256, phni, phnj, phproj);
    gemm_edge<12, true><<<TB_E, 512, MM_SMEM>>>(pfs, pwp + (size_t)7 * WPSZ,
                                                bias_e + 256, attn + 256, src, dst);
    node_gather<<<(N_NODES * 32 + 255) / 256, blk>>>(src);

    gemm64<<<dim3(NB_N, 1), blk>>>(ph, Wf, bf, (float*)d_out, nullptr, N_NODES, 64, 64);
}